// round 4
// baseline (speedup 1.0000x reference)
#include <cuda_runtime.h>
#include <cuda_bf16.h>
#include <math.h>
#include <stdint.h>

#define BB 8
#define NN 2048
#define DD 512
#define MM (BB * NN)
#define NEPS 1e-5f

// Scratch (__device__ globals — allocation-free per harness rules)
__device__ uint16_t g_Xhi[(size_t)MM * DD];
__device__ uint16_t g_Xlo[(size_t)MM * DD];
__device__ uint16_t g_Whi[(size_t)DD * DD];
__device__ uint16_t g_Wlo[(size_t)DD * DD];
__device__ uint16_t g_Shi[(size_t)BB * NN * NN];
__device__ uint16_t g_Slo[(size_t)BB * NN * NN];
__device__ uint16_t g_Vhi[(size_t)MM * DD];
__device__ uint16_t g_Vlo[(size_t)MM * DD];
__device__ float    g_rnorm[MM];

// ---------------------------------------------------------------------------
// helpers
// ---------------------------------------------------------------------------
__device__ __forceinline__ uint32_t smem_u32(const void* p) {
    uint32_t a;
    asm("{ .reg .u64 t; cvta.to.shared.u64 t, %1; cvt.u32.u64 %0, t; }"
        : "=r"(a) : "l"(p));
    return a;
}
__device__ __forceinline__ void cp16(uint32_t d, const void* g) {
    asm volatile("cp.async.cg.shared.global [%0], [%1], 16;" :: "r"(d), "l"(g));
}
__device__ __forceinline__ void cpcommit() {
    asm volatile("cp.async.commit_group;" ::: "memory");
}
template <int N> __device__ __forceinline__ void cpwait() {
    asm volatile("cp.async.wait_group %0;" :: "n"(N) : "memory");
}
__device__ __forceinline__ void ldsm_x4(uint32_t* r, uint32_t a) {
    asm volatile("ldmatrix.sync.aligned.m8n8.x4.shared.b16 {%0,%1,%2,%3}, [%4];"
                 : "=r"(r[0]), "=r"(r[1]), "=r"(r[2]), "=r"(r[3]) : "r"(a));
}
__device__ __forceinline__ void ldsm_x4t(uint32_t* r, uint32_t a) {
    asm volatile("ldmatrix.sync.aligned.m8n8.x4.trans.shared.b16 {%0,%1,%2,%3}, [%4];"
                 : "=r"(r[0]), "=r"(r[1]), "=r"(r[2]), "=r"(r[3]) : "r"(a));
}
__device__ __forceinline__ void mma16816(float* d, const uint32_t* a, const uint32_t* b) {
    asm volatile(
        "mma.sync.aligned.m16n8k16.row.col.f32.bf16.bf16.f32 "
        "{%0,%1,%2,%3}, {%4,%5,%6,%7}, {%8,%9}, {%0,%1,%2,%3};"
        : "+f"(d[0]), "+f"(d[1]), "+f"(d[2]), "+f"(d[3])
        : "r"(a[0]), "r"(a[1]), "r"(a[2]), "r"(a[3]), "r"(b[0]), "r"(b[1]));
}
__device__ __forceinline__ uint32_t packsplit(float x0, float x1, uint32_t& lo) {
    uint32_t h;
    asm("cvt.rn.bf16x2.f32 %0, %1, %2;" : "=r"(h) : "f"(x1), "f"(x0));
    float r0 = x0 - __uint_as_float(h << 16);
    float r1 = x1 - __uint_as_float(h & 0xffff0000u);
    asm("cvt.rn.bf16x2.f32 %0, %1, %2;" : "=r"(lo) : "f"(r1), "f"(r0));
    return h;
}
__device__ __forceinline__ void split4(float4 x, uint2& hi, uint2& lo) {
    uint32_t l0, l1;
    uint32_t h0 = packsplit(x.x, x.y, l0);
    uint32_t h1 = packsplit(x.z, x.w, l1);
    hi = make_uint2(h0, h1);
    lo = make_uint2(l0, l1);
}

// ---------------------------------------------------------------------------
// compute one K=32 chunk: acc[2][8][4] += A(128x32) * B^T, bf16x3 products
// SMEM stage layout: A hi @0 (pitch 80), A lo @10240, B hi @20480 (pitch BP), B lo @BLO
// ---------------------------------------------------------------------------
template <bool BT, int BLO, int BP>
__device__ __forceinline__ void compute_chunk(uint32_t sb, int wm, int wn, int lane,
                                              float acc[2][8][4]) {
    #pragma unroll
    for (int s = 0; s < 2; s++) {
        uint32_t Ah[2][4], Al[2][4], Bh[8][2], Bl[8][2];
        uint32_t aaddr = sb + (uint32_t)((wm * 32 + (lane & 15)) * 80
                                         + (s * 16 + (lane >> 4) * 8) * 2);
        ldsm_x4(Ah[0], aaddr);
        ldsm_x4(Ah[1], aaddr + 16 * 80);
        ldsm_x4(Al[0], aaddr + 10240);
        ldsm_x4(Al[1], aaddr + 10240 + 16 * 80);

        #pragma unroll
        for (int p = 0; p < 4; p++) {
            uint32_t r[4], baddr;
            if (!BT) {
                int n  = wn * 64 + p * 16 + (lane >> 4) * 8 + (lane & 7);
                int kc = s * 16 + ((lane >> 3) & 1) * 8;
                baddr = sb + 20480u + (uint32_t)(n * BP + kc * 2);
                ldsm_x4(r, baddr);
                Bh[2*p][0] = r[0]; Bh[2*p][1] = r[1];
                Bh[2*p+1][0] = r[2]; Bh[2*p+1][1] = r[3];
                ldsm_x4(r, baddr + (uint32_t)(BLO - 20480));
                Bl[2*p][0] = r[0]; Bl[2*p][1] = r[1];
                Bl[2*p+1][0] = r[2]; Bl[2*p+1][1] = r[3];
            } else {
                int k = s * 16 + (lane & 7) + ((lane >> 3) & 1) * 8;
                int n = wn * 64 + p * 16 + (lane >> 4) * 8;
                baddr = sb + 20480u + (uint32_t)(k * BP + n * 2);
                ldsm_x4t(r, baddr);
                Bh[2*p][0] = r[0]; Bh[2*p][1] = r[1];
                Bh[2*p+1][0] = r[2]; Bh[2*p+1][1] = r[3];
                ldsm_x4t(r, baddr + (uint32_t)(BLO - 20480));
                Bl[2*p][0] = r[0]; Bl[2*p][1] = r[1];
                Bl[2*p+1][0] = r[2]; Bl[2*p+1][1] = r[3];
            }
        }
        #pragma unroll
        for (int mf = 0; mf < 2; mf++)
            #pragma unroll
            for (int nf = 0; nf < 8; nf++) {
                mma16816(acc[mf][nf], Ah[mf], Bh[nf]);
                mma16816(acc[mf][nf], Ah[mf], Bl[nf]);
                mma16816(acc[mf][nf], Al[mf], Bh[nf]);
            }
    }
}

#define STRIDE_F 40960
#define STRIDE_O 37888

// cp.async stage: A[128 rows x 32 cols bf16, ld=512] hi/lo + B same (pitch 80)
__device__ __forceinline__ void stage_f(uint32_t st,
                                        const uint16_t* __restrict__ Ah,
                                        const uint16_t* __restrict__ Al,
                                        const uint16_t* __restrict__ Bh,
                                        const uint16_t* __restrict__ Bl,
                                        int kc, int tid) {
    const uint16_t* srcs[4] = {Ah, Al, Bh, Bl};
    #pragma unroll
    for (int q = 0; q < 8; q++) {
        const int arr = q >> 1;
        const int row = (q & 1) * 64 + (tid >> 2);
        const int seg = tid & 3;
        cp16(st + arr * 10240u + row * 80u + seg * 16u,
             srcs[arr] + (size_t)row * DD + kc + seg * 8);
    }
}

// cp.async stage for out: S[128 x 32, ld=2048] hi/lo (pitch 80) + V[32 x 128, ld=512] hi/lo (pitch 272)
__device__ __forceinline__ void stage_o(uint32_t st,
                                        const uint16_t* __restrict__ Sh,
                                        const uint16_t* __restrict__ Sl,
                                        const uint16_t* __restrict__ Vh,
                                        const uint16_t* __restrict__ Vl,
                                        int kc, int tid) {
    #pragma unroll
    for (int q = 0; q < 4; q++) {
        const int arr = q >> 1;
        const int row = (q & 1) * 64 + (tid >> 2);
        const int seg = tid & 3;
        const uint16_t* s = arr ? Sl : Sh;
        cp16(st + arr * 10240u + row * 80u + seg * 16u,
             s + (size_t)row * NN + kc + seg * 8);
    }
    #pragma unroll
    for (int q = 4; q < 8; q++) {
        const int lo  = (q >= 6);
        const int row = (q & 1) * 16 + (tid >> 4);
        const int seg = tid & 15;
        const uint16_t* s = lo ? Vl : Vh;
        cp16(st + 20480u + lo * 8704u + row * 272u + seg * 16u,
             s + (size_t)(kc + row) * DD + seg * 8);
    }
}

// ---------------------------------------------------------------------------
// prologue: split X and W to bf16 hi/lo
// ---------------------------------------------------------------------------
__global__ __launch_bounds__(256) void split_kernel(const float* __restrict__ X,
                                                    const float* __restrict__ W) {
    const size_t NX = (size_t)MM * DD / 4;
    const size_t NW = (size_t)DD * DD / 4;
    size_t i = (size_t)blockIdx.x * 256 + threadIdx.x;
    if (i < NX) {
        float4 x = ((const float4*)X)[i];
        uint2 hi, lo; split4(x, hi, lo);
        *(uint2*)(g_Xhi + i * 4) = hi;
        *(uint2*)(g_Xlo + i * 4) = lo;
    } else if (i < NX + NW) {
        size_t j = i - NX;
        float4 x = ((const float4*)W)[j];
        uint2 hi, lo; split4(x, hi, lo);
        *(uint2*)(g_Whi + j * 4) = hi;
        *(uint2*)(g_Wlo + j * 4) = lo;
    }
    if (i < MM) g_rnorm[i] = 0.0f;
}

// ---------------------------------------------------------------------------
// Kernel 1: V = elu(X @ W^T + b) -> g_Vhi/g_Vlo [m][e]
// ---------------------------------------------------------------------------
__global__ __launch_bounds__(256, 1)
void vproj_kernel(const float* __restrict__ bias) {
    extern __shared__ __align__(16) uint8_t smem[];
    const int tid = threadIdx.x, wid = tid >> 5, lane = tid & 31;
    const int wm = wid & 3, wn = wid >> 2;
    const int eBase = blockIdx.x * 128, mBase = blockIdx.y * 128;
    const uint16_t* Ah = g_Xhi + (size_t)mBase * DD;
    const uint16_t* Al = g_Xlo + (size_t)mBase * DD;
    const uint16_t* Bh = g_Whi + (size_t)eBase * DD;
    const uint16_t* Bl = g_Wlo + (size_t)eBase * DD;
    const uint32_t sb = smem_u32(smem);

    float acc[2][8][4] = {};
    stage_f(sb, Ah, Al, Bh, Bl, 0, tid);  cpcommit();
    stage_f(sb + STRIDE_F, Ah, Al, Bh, Bl, 32, tid);  cpcommit();
    int cur = 0, nxt = 2;
    for (int c = 0; c < 16; c++) {
        cpwait<1>(); __syncthreads();
        compute_chunk<false, 30720, 80>(sb + cur * STRIDE_F, wm, wn, lane, acc);
        __syncthreads();
        if (c + 2 < 16) stage_f(sb + nxt * STRIDE_F, Ah, Al, Bh, Bl, (c + 2) * 32, tid);
        cpcommit();
        cur = (cur == 2) ? 0 : cur + 1;
        nxt = (nxt == 2) ? 0 : nxt + 1;
    }

    // epilogue: bias+elu -> per-warp bounce -> coalesced hi/lo stores
    __syncthreads();
    float* buf = (float*)(smem + wid * 8704);
    const int gr0 = mBase + wm * 32, gc0 = eBase + wn * 64;
    const int r = lane >> 2, cc2 = (lane & 3) * 2;
    #pragma unroll
    for (int mf = 0; mf < 2; mf++)
        #pragma unroll
        for (int nf = 0; nf < 8; nf++) {
            const int col = nf * 8 + cc2;
            float2 bv = *(const float2*)(bias + gc0 + col);
            float v0 = acc[mf][nf][0] + bv.x;
            float v1 = acc[mf][nf][1] + bv.y;
            float v2 = acc[mf][nf][2] + bv.x;
            float v3 = acc[mf][nf][3] + bv.y;
            v0 = v0 > 0.0f ? v0 : expm1f(v0);
            v1 = v1 > 0.0f ? v1 : expm1f(v1);
            v2 = v2 > 0.0f ? v2 : expm1f(v2);
            v3 = v3 > 0.0f ? v3 : expm1f(v3);
            *(float2*)&buf[(mf * 16 + r) * 68 + col]     = make_float2(v0, v1);
            *(float2*)&buf[(mf * 16 + r + 8) * 68 + col] = make_float2(v2, v3);
        }
    __syncwarp();
    #pragma unroll
    for (int it = 0; it < 16; it++) {
        const int row = it * 2 + (lane >> 4);
        const int col = (lane & 15) * 4;
        float4 v = *(float4*)&buf[row * 68 + col];
        uint32_t lo0, lo1;
        uint32_t hi0 = packsplit(v.x, v.y, lo0);
        uint32_t hi1 = packsplit(v.z, v.w, lo1);
        size_t off = (size_t)(gr0 + row) * DD + gc0 + col;
        *(uint2*)(g_Vhi + off) = make_uint2(hi0, hi1);
        *(uint2*)(g_Vlo + off) = make_uint2(lo0, lo1);
    }
}

// ---------------------------------------------------------------------------
// Kernel 2: S = (X X^T / sqrt(D)) * mask -> g_Shi/g_Slo + rnorm atomics
// ---------------------------------------------------------------------------
__global__ __launch_bounds__(256, 1)
void scores_kernel(const float* __restrict__ mask) {
    extern __shared__ __align__(16) uint8_t smem[];
    const int tid = threadIdx.x, wid = tid >> 5, lane = tid & 31;
    const int wm = wid & 3, wn = wid >> 2;
    const int b = blockIdx.z;
    const int iBase = blockIdx.y * 128, jBase = blockIdx.x * 128;
    const uint16_t* Ah = g_Xhi + (size_t)(b * NN + iBase) * DD;
    const uint16_t* Al = g_Xlo + (size_t)(b * NN + iBase) * DD;
    const uint16_t* Bh = g_Xhi + (size_t)(b * NN + jBase) * DD;
    const uint16_t* Bl = g_Xlo + (size_t)(b * NN + jBase) * DD;
    const float* Mb = mask + (size_t)b * NN * NN;
    uint16_t* Sh = g_Shi + (size_t)b * NN * NN;
    uint16_t* Sl = g_Slo + (size_t)b * NN * NN;
    const uint32_t sb = smem_u32(smem);

    float acc[2][8][4] = {};
    stage_f(sb, Ah, Al, Bh, Bl, 0, tid);  cpcommit();
    stage_f(sb + STRIDE_F, Ah, Al, Bh, Bl, 32, tid);  cpcommit();
    int cur = 0, nxt = 2;
    for (int c = 0; c < 16; c++) {
        cpwait<1>(); __syncthreads();
        compute_chunk<false, 30720, 80>(sb + cur * STRIDE_F, wm, wn, lane, acc);
        __syncthreads();
        if (c + 2 < 16) stage_f(sb + nxt * STRIDE_F, Ah, Al, Bh, Bl, (c + 2) * 32, tid);
        cpcommit();
        cur = (cur == 2) ? 0 : cur + 1;
        nxt = (nxt == 2) ? 0 : nxt + 1;
    }

    // epilogue
    __syncthreads();
    const uint32_t bufa = sb + wid * 8704u;
    float* buf = (float*)(smem + wid * 8704);
    const int gr0 = iBase + wm * 32, gc0 = jBase + wn * 64;
    // coalesced mask tile load into bounce buffer (pitch 272B = 68 floats)
    #pragma unroll
    for (int q = 0; q < 16; q++) {
        const int idx = q * 32 + lane;
        const int row = idx >> 4, seg = idx & 15;
        cp16(bufa + row * 272u + seg * 16u,
             Mb + (size_t)(gr0 + row) * NN + gc0 + seg * 4);
    }
    cpcommit(); cpwait<0>(); __syncwarp();

    const float invt = 0.044194173824159216f;  // 1/sqrt(512)
    const int r = lane >> 2, cc2 = (lane & 3) * 2;
    #pragma unroll
    for (int mf = 0; mf < 2; mf++) {
        float ss0 = 0.0f, ss8 = 0.0f;
        #pragma unroll
        for (int nf = 0; nf < 8; nf++) {
            const int col = nf * 8 + cc2;
            float2 m0 = *(float2*)&buf[(mf * 16 + r) * 68 + col];
            float2 m8 = *(float2*)&buf[(mf * 16 + r + 8) * 68 + col];
            float s0 = acc[mf][nf][0] * invt * m0.x;
            float s1 = acc[mf][nf][1] * invt * m0.y;
            float s2 = acc[mf][nf][2] * invt * m8.x;
            float s3 = acc[mf][nf][3] * invt * m8.y;
            ss0 += s0 * s0 + s1 * s1;
            ss8 += s2 * s2 + s3 * s3;
            *(float2*)&buf[(mf * 16 + r) * 68 + col]     = make_float2(s0, s1);
            *(float2*)&buf[(mf * 16 + r + 8) * 68 + col] = make_float2(s2, s3);
        }
        ss0 += __shfl_xor_sync(0xffffffffu, ss0, 1);
        ss0 += __shfl_xor_sync(0xffffffffu, ss0, 2);
        ss8 += __shfl_xor_sync(0xffffffffu, ss8, 1);
        ss8 += __shfl_xor_sync(0xffffffffu, ss8, 2);
        if ((lane & 3) == 0) {
            atomicAdd(&g_rnorm[b * NN + gr0 + mf * 16 + r], ss0);
            atomicAdd(&g_rnorm[b * NN + gr0 + mf * 16 + r + 8], ss8);
        }
    }
    __syncwarp();
    #pragma unroll
    for (int it = 0; it < 16; it++) {
        const int row = it * 2 + (lane >> 4);
        const int col = (lane & 15) * 4;
        float4 v = *(float4*)&buf[row * 68 + col];
        uint32_t lo0, lo1;
        uint32_t hi0 = packsplit(v.x, v.y, lo0);
        uint32_t hi1 = packsplit(v.z, v.w, lo1);
        size_t off = (size_t)(gr0 + row) * NN + gc0 + col;
        *(uint2*)(Sh + off) = make_uint2(hi0, hi1);
        *(uint2*)(Sl + off) = make_uint2(lo0, lo1);
    }
}

// ---------------------------------------------------------------------------
// Kernel 3: out = diag(1/max(||S row||,eps)) * (S @ V)
// ---------------------------------------------------------------------------
__global__ __launch_bounds__(256, 1)
void out_kernel(float* __restrict__ out) {
    extern __shared__ __align__(16) uint8_t smem[];
    const int tid = threadIdx.x, wid = tid >> 5, lane = tid & 31;
    const int wm = wid & 3, wn = wid >> 2;
    const int b = blockIdx.z;
    const int iBase = blockIdx.y * 128, eBase = blockIdx.x * 128;
    const uint16_t* Sh = g_Shi + (size_t)b * NN * NN + (size_t)iBase * NN;
    const uint16_t* Sl = g_Slo + (size_t)b * NN * NN + (size_t)iBase * NN;
    const uint16_t* Vh = g_Vhi + (size_t)b * NN * DD + eBase;
    const uint16_t* Vl = g_Vlo + (size_t)b * NN * DD + eBase;
    const uint32_t sb = smem_u32(smem);

    float acc[2][8][4] = {};
    stage_o(sb, Sh, Sl, Vh, Vl, 0, tid);  cpcommit();
    stage_o(sb + STRIDE_O, Sh, Sl, Vh, Vl, 32, tid);  cpcommit();
    int cur = 0, nxt = 2;
    for (int c = 0; c < 64; c++) {
        cpwait<1>(); __syncthreads();
        compute_chunk<true, 29184, 272>(sb + cur * STRIDE_O, wm, wn, lane, acc);
        __syncthreads();
        if (c + 2 < 64) stage_o(sb + nxt * STRIDE_O, Sh, Sl, Vh, Vl, (c + 2) * 32, tid);
        cpcommit();
        cur = (cur == 2) ? 0 : cur + 1;
        nxt = (nxt == 2) ? 0 : nxt + 1;
    }

    // epilogue: bounce + rescale + coalesced f32 stores
    __syncthreads();
    float* buf = (float*)(smem + wid * 8704);
    const int gr0 = iBase + wm * 32, gc0 = eBase + wn * 64;
    const int r = lane >> 2, cc2 = (lane & 3) * 2;
    #pragma unroll
    for (int mf = 0; mf < 2; mf++)
        #pragma unroll
        for (int nf = 0; nf < 8; nf++) {
            const int col = nf * 8 + cc2;
            *(float2*)&buf[(mf * 16 + r) * 68 + col] =
                make_float2(acc[mf][nf][0], acc[mf][nf][1]);
            *(float2*)&buf[(mf * 16 + r + 8) * 68 + col] =
                make_float2(acc[mf][nf][2], acc[mf][nf][3]);
        }
    __syncwarp();
    #pragma unroll
    for (int it = 0; it < 16; it++) {
        const int row = it * 2 + (lane >> 4);
        const int col = (lane & 15) * 4;
        const int gi = gr0 + row;
        float4 v = *(float4*)&buf[row * 68 + col];
        float inv = 1.0f / fmaxf(sqrtf(g_rnorm[b * NN + gi]), NEPS);
        v.x *= inv; v.y *= inv; v.z *= inv; v.w *= inv;
        *(float4*)(out + ((size_t)b * NN + gi) * DD + gc0 + col) = v;
    }
}

// ---------------------------------------------------------------------------
extern "C" void kernel_launch(void* const* d_in, const int* in_sizes, int n_in,
                              void* d_out, int out_size) {
    const float* X    = (const float*)d_in[0];
    const float* mask = (const float*)d_in[1];
    const float* W    = (const float*)d_in[2];
    const float* bias = (const float*)d_in[3];
    float* out = (float*)d_out;

    static int attr_done = 0;
    if (!attr_done) {
        cudaFuncSetAttribute(vproj_kernel,  cudaFuncAttributeMaxDynamicSharedMemorySize, 3 * STRIDE_F);
        cudaFuncSetAttribute(scores_kernel, cudaFuncAttributeMaxDynamicSharedMemorySize, 3 * STRIDE_F);
        cudaFuncSetAttribute(out_kernel,    cudaFuncAttributeMaxDynamicSharedMemorySize, 3 * STRIDE_O);
        attr_done = 1;
    }

    const int NSPLIT = (MM * DD + DD * DD) / 4;
    split_kernel<<<(NSPLIT + 255) / 256, 256>>>(X, W);
    vproj_kernel<<<dim3(4, 128), 256, 3 * STRIDE_F>>>(bias);
    scores_kernel<<<dim3(16, 16, 8), 256, 3 * STRIDE_F>>>(mask);
    out_kernel<<<dim3(4, 16, 8), 256, 3 * STRIDE_O>>>(out);
}

// round 5
// speedup vs baseline: 1.2349x; 1.2349x over previous
#include <cuda_runtime.h>
#include <cuda_bf16.h>
#include <math.h>
#include <stdint.h>

#define BB 8
#define NN 2048
#define DD 512
#define MM (BB * NN)
#define NEPS 1e-5f

// Scratch (__device__ globals — allocation-free per harness rules)
__device__ uint16_t g_Xhi[(size_t)MM * DD];
__device__ uint16_t g_Xlo[(size_t)MM * DD];
__device__ uint16_t g_Whi[(size_t)DD * DD];
__device__ uint16_t g_Wlo[(size_t)DD * DD];
__device__ uint16_t g_Shi[(size_t)BB * NN * NN];
__device__ uint16_t g_Slo[(size_t)BB * NN * NN];
__device__ uint16_t g_Vhi[(size_t)MM * DD];
__device__ uint16_t g_Vlo[(size_t)MM * DD];
__device__ float    g_rnorm[MM];

// ---------------------------------------------------------------------------
// helpers
// ---------------------------------------------------------------------------
__device__ __forceinline__ uint32_t smem_u32(const void* p) {
    uint32_t a;
    asm("{ .reg .u64 t; cvta.to.shared.u64 t, %1; cvt.u32.u64 %0, t; }"
        : "=r"(a) : "l"(p));
    return a;
}
__device__ __forceinline__ void cp16(uint32_t d, const void* g) {
    asm volatile("cp.async.cg.shared.global [%0], [%1], 16;" :: "r"(d), "l"(g));
}
__device__ __forceinline__ void cpcommit() {
    asm volatile("cp.async.commit_group;" ::: "memory");
}
template <int N> __device__ __forceinline__ void cpwait() {
    asm volatile("cp.async.wait_group %0;" :: "n"(N) : "memory");
}
__device__ __forceinline__ void ldsm_x4(uint32_t* r, uint32_t a) {
    asm volatile("ldmatrix.sync.aligned.m8n8.x4.shared.b16 {%0,%1,%2,%3}, [%4];"
                 : "=r"(r[0]), "=r"(r[1]), "=r"(r[2]), "=r"(r[3]) : "r"(a));
}
__device__ __forceinline__ void ldsm_x4t(uint32_t* r, uint32_t a) {
    asm volatile("ldmatrix.sync.aligned.m8n8.x4.trans.shared.b16 {%0,%1,%2,%3}, [%4];"
                 : "=r"(r[0]), "=r"(r[1]), "=r"(r[2]), "=r"(r[3]) : "r"(a));
}
__device__ __forceinline__ void mma16816(float* d, const uint32_t* a, const uint32_t* b) {
    asm volatile(
        "mma.sync.aligned.m16n8k16.row.col.f32.bf16.bf16.f32 "
        "{%0,%1,%2,%3}, {%4,%5,%6,%7}, {%8,%9}, {%0,%1,%2,%3};"
        : "+f"(d[0]), "+f"(d[1]), "+f"(d[2]), "+f"(d[3])
        : "r"(a[0]), "r"(a[1]), "r"(a[2]), "r"(a[3]), "r"(b[0]), "r"(b[1]));
}
__device__ __forceinline__ uint32_t packsplit(float x0, float x1, uint32_t& lo) {
    uint32_t h;
    asm("cvt.rn.bf16x2.f32 %0, %1, %2;" : "=r"(h) : "f"(x1), "f"(x0));
    float r0 = x0 - __uint_as_float(h << 16);
    float r1 = x1 - __uint_as_float(h & 0xffff0000u);
    asm("cvt.rn.bf16x2.f32 %0, %1, %2;" : "=r"(lo) : "f"(r1), "f"(r0));
    return h;
}
__device__ __forceinline__ void split4(float4 x, uint2& hi, uint2& lo) {
    uint32_t l0, l1;
    uint32_t h0 = packsplit(x.x, x.y, l0);
    uint32_t h1 = packsplit(x.z, x.w, l1);
    hi = make_uint2(h0, h1);
    lo = make_uint2(l0, l1);
}

// ---------------------------------------------------------------------------
// compute one K=32 chunk: acc[2][8][4] += A(128x32) * B^T, bf16x3 products
// B fragments loaded per-p to minimize live registers (2-CTA occupancy).
// SMEM stage layout: A hi @0 (pitch 80), A lo @10240, B hi @20480 (pitch BP), B lo @BLO
// ---------------------------------------------------------------------------
template <bool BT, int BLO, int BP>
__device__ __forceinline__ void compute_chunk(uint32_t sb, int wm, int wn, int lane,
                                              float acc[2][8][4]) {
    #pragma unroll
    for (int s = 0; s < 2; s++) {
        uint32_t Ah[2][4], Al[2][4];
        uint32_t aaddr = sb + (uint32_t)((wm * 32 + (lane & 15)) * 80
                                         + (s * 16 + (lane >> 4) * 8) * 2);
        ldsm_x4(Ah[0], aaddr);
        ldsm_x4(Ah[1], aaddr + 16 * 80);
        ldsm_x4(Al[0], aaddr + 10240);
        ldsm_x4(Al[1], aaddr + 10240 + 16 * 80);

        #pragma unroll
        for (int p = 0; p < 4; p++) {
            uint32_t rh[4], rl[4], baddr;
            if (!BT) {
                int n  = wn * 64 + p * 16 + (lane >> 4) * 8 + (lane & 7);
                int kc = s * 16 + ((lane >> 3) & 1) * 8;
                baddr = sb + 20480u + (uint32_t)(n * BP + kc * 2);
                ldsm_x4(rh, baddr);
                ldsm_x4(rl, baddr + (uint32_t)(BLO - 20480));
            } else {
                int k = s * 16 + (lane & 7) + ((lane >> 3) & 1) * 8;
                int n = wn * 64 + p * 16 + (lane >> 4) * 8;
                baddr = sb + 20480u + (uint32_t)(k * BP + n * 2);
                ldsm_x4t(rh, baddr);
                ldsm_x4t(rl, baddr + (uint32_t)(BLO - 20480));
            }
            #pragma unroll
            for (int mf = 0; mf < 2; mf++) {
                mma16816(acc[mf][2*p],   Ah[mf], &rh[0]);
                mma16816(acc[mf][2*p],   Ah[mf], &rl[0]);
                mma16816(acc[mf][2*p],   Al[mf], &rh[0]);
                mma16816(acc[mf][2*p+1], Ah[mf], &rh[2]);
                mma16816(acc[mf][2*p+1], Ah[mf], &rl[2]);
                mma16816(acc[mf][2*p+1], Al[mf], &rh[2]);
            }
        }
    }
}

#define STRIDE_F 40960
#define STRIDE_O 37888

// cp.async stage: A[128 x 32 bf16, ld=512] hi/lo + B same (pitch 80)
__device__ __forceinline__ void stage_f(uint32_t st,
                                        const uint16_t* __restrict__ Ah,
                                        const uint16_t* __restrict__ Al,
                                        const uint16_t* __restrict__ Bh,
                                        const uint16_t* __restrict__ Bl,
                                        int kc, int tid) {
    const uint16_t* srcs[4] = {Ah, Al, Bh, Bl};
    #pragma unroll
    for (int q = 0; q < 8; q++) {
        const int arr = q >> 1;
        const int row = (q & 1) * 64 + (tid >> 2);
        const int seg = tid & 3;
        cp16(st + arr * 10240u + row * 80u + seg * 16u,
             srcs[arr] + (size_t)row * DD + kc + seg * 8);
    }
}

// cp.async stage for out: S[128 x 32, ld=2048] hi/lo (pitch 80) + V[32 x 128, ld=512] hi/lo (pitch 272)
__device__ __forceinline__ void stage_o(uint32_t st,
                                        const uint16_t* __restrict__ Sh,
                                        const uint16_t* __restrict__ Sl,
                                        const uint16_t* __restrict__ Vh,
                                        const uint16_t* __restrict__ Vl,
                                        int kc, int tid) {
    #pragma unroll
    for (int q = 0; q < 4; q++) {
        const int arr = q >> 1;
        const int row = (q & 1) * 64 + (tid >> 2);
        const int seg = tid & 3;
        const uint16_t* s = arr ? Sl : Sh;
        cp16(st + arr * 10240u + row * 80u + seg * 16u,
             s + (size_t)row * NN + kc + seg * 8);
    }
    #pragma unroll
    for (int q = 4; q < 8; q++) {
        const int lo  = (q >= 6);
        const int row = (q & 1) * 16 + (tid >> 4);
        const int seg = tid & 15;
        const uint16_t* s = lo ? Vl : Vh;
        cp16(st + 20480u + lo * 8704u + row * 272u + seg * 16u,
             s + (size_t)(kc + row) * DD + seg * 8);
    }
}

// ---------------------------------------------------------------------------
// prologue: split X and W to bf16 hi/lo
// ---------------------------------------------------------------------------
__global__ __launch_bounds__(256) void split_kernel(const float* __restrict__ X,
                                                    const float* __restrict__ W) {
    const size_t NX = (size_t)MM * DD / 4;
    const size_t NW = (size_t)DD * DD / 4;
    size_t i = (size_t)blockIdx.x * 256 + threadIdx.x;
    if (i < NX) {
        float4 x = ((const float4*)X)[i];
        uint2 hi, lo; split4(x, hi, lo);
        *(uint2*)(g_Xhi + i * 4) = hi;
        *(uint2*)(g_Xlo + i * 4) = lo;
    } else if (i < NX + NW) {
        size_t j = i - NX;
        float4 x = ((const float4*)W)[j];
        uint2 hi, lo; split4(x, hi, lo);
        *(uint2*)(g_Whi + j * 4) = hi;
        *(uint2*)(g_Wlo + j * 4) = lo;
    }
    if (i < MM) g_rnorm[i] = 0.0f;
}

// ---------------------------------------------------------------------------
// Kernel 1: V = elu(X @ W^T + b) -> g_Vhi/g_Vlo [m][e]   (2-stage pipeline)
// ---------------------------------------------------------------------------
__global__ __launch_bounds__(256, 2)
void vproj_kernel(const float* __restrict__ bias) {
    extern __shared__ __align__(16) uint8_t smem[];
    const int tid = threadIdx.x, wid = tid >> 5, lane = tid & 31;
    const int wm = wid & 3, wn = wid >> 2;
    const int eBase = blockIdx.x * 128, mBase = blockIdx.y * 128;
    const uint16_t* Ah = g_Xhi + (size_t)mBase * DD;
    const uint16_t* Al = g_Xlo + (size_t)mBase * DD;
    const uint16_t* Bh = g_Whi + (size_t)eBase * DD;
    const uint16_t* Bl = g_Wlo + (size_t)eBase * DD;
    const uint32_t sb = smem_u32(smem);

    float acc[2][8][4] = {};
    stage_f(sb, Ah, Al, Bh, Bl, 0, tid);  cpcommit();
    for (int c = 0; c < 16; c++) {
        cpwait<0>(); __syncthreads();
        if (c + 1 < 16)
            stage_f(sb + ((c + 1) & 1) * STRIDE_F, Ah, Al, Bh, Bl, (c + 1) * 32, tid);
        cpcommit();
        compute_chunk<false, 30720, 80>(sb + (c & 1) * STRIDE_F, wm, wn, lane, acc);
    }

    // epilogue: bias+elu -> per-warp bounce -> coalesced hi/lo stores
    __syncthreads();
    float* buf = (float*)(smem + wid * 8704);
    const int gr0 = mBase + wm * 32, gc0 = eBase + wn * 64;
    const int r = lane >> 2, cc2 = (lane & 3) * 2;
    #pragma unroll
    for (int mf = 0; mf < 2; mf++)
        #pragma unroll
        for (int nf = 0; nf < 8; nf++) {
            const int col = nf * 8 + cc2;
            float2 bv = *(const float2*)(bias + gc0 + col);
            float v0 = acc[mf][nf][0] + bv.x;
            float v1 = acc[mf][nf][1] + bv.y;
            float v2 = acc[mf][nf][2] + bv.x;
            float v3 = acc[mf][nf][3] + bv.y;
            v0 = v0 > 0.0f ? v0 : expm1f(v0);
            v1 = v1 > 0.0f ? v1 : expm1f(v1);
            v2 = v2 > 0.0f ? v2 : expm1f(v2);
            v3 = v3 > 0.0f ? v3 : expm1f(v3);
            *(float2*)&buf[(mf * 16 + r) * 68 + col]     = make_float2(v0, v1);
            *(float2*)&buf[(mf * 16 + r + 8) * 68 + col] = make_float2(v2, v3);
        }
    __syncwarp();
    #pragma unroll
    for (int it = 0; it < 16; it++) {
        const int row = it * 2 + (lane >> 4);
        const int col = (lane & 15) * 4;
        float4 v = *(float4*)&buf[row * 68 + col];
        uint32_t lo0, lo1;
        uint32_t hi0 = packsplit(v.x, v.y, lo0);
        uint32_t hi1 = packsplit(v.z, v.w, lo1);
        size_t off = (size_t)(gr0 + row) * DD + gc0 + col;
        *(uint2*)(g_Vhi + off) = make_uint2(hi0, hi1);
        *(uint2*)(g_Vlo + off) = make_uint2(lo0, lo1);
    }
}

// ---------------------------------------------------------------------------
// Kernel 2: S = (X X^T / sqrt(D)) * mask -> g_Shi/g_Slo + rnorm atomics
// ---------------------------------------------------------------------------
__global__ __launch_bounds__(256, 2)
void scores_kernel(const float* __restrict__ mask) {
    extern __shared__ __align__(16) uint8_t smem[];
    const int tid = threadIdx.x, wid = tid >> 5, lane = tid & 31;
    const int wm = wid & 3, wn = wid >> 2;
    const int b = blockIdx.z;
    const int iBase = blockIdx.y * 128, jBase = blockIdx.x * 128;
    const uint16_t* Ah = g_Xhi + (size_t)(b * NN + iBase) * DD;
    const uint16_t* Al = g_Xlo + (size_t)(b * NN + iBase) * DD;
    const uint16_t* Bh = g_Xhi + (size_t)(b * NN + jBase) * DD;
    const uint16_t* Bl = g_Xlo + (size_t)(b * NN + jBase) * DD;
    const float* Mb = mask + (size_t)b * NN * NN;
    uint16_t* Sh = g_Shi + (size_t)b * NN * NN;
    uint16_t* Sl = g_Slo + (size_t)b * NN * NN;
    const uint32_t sb = smem_u32(smem);

    float acc[2][8][4] = {};
    stage_f(sb, Ah, Al, Bh, Bl, 0, tid);  cpcommit();
    for (int c = 0; c < 16; c++) {
        cpwait<0>(); __syncthreads();
        if (c + 1 < 16)
            stage_f(sb + ((c + 1) & 1) * STRIDE_F, Ah, Al, Bh, Bl, (c + 1) * 32, tid);
        cpcommit();
        compute_chunk<false, 30720, 80>(sb + (c & 1) * STRIDE_F, wm, wn, lane, acc);
    }

    // epilogue
    __syncthreads();
    const uint32_t bufa = sb + wid * 8704u;
    float* buf = (float*)(smem + wid * 8704);
    const int gr0 = iBase + wm * 32, gc0 = jBase + wn * 64;
    #pragma unroll
    for (int q = 0; q < 16; q++) {
        const int idx = q * 32 + lane;
        const int row = idx >> 4, seg = idx & 15;
        cp16(bufa + row * 272u + seg * 16u,
             Mb + (size_t)(gr0 + row) * NN + gc0 + seg * 4);
    }
    cpcommit(); cpwait<0>(); __syncwarp();

    const float invt = 0.044194173824159216f;  // 1/sqrt(512)
    const int r = lane >> 2, cc2 = (lane & 3) * 2;
    #pragma unroll
    for (int mf = 0; mf < 2; mf++) {
        float ss0 = 0.0f, ss8 = 0.0f;
        #pragma unroll
        for (int nf = 0; nf < 8; nf++) {
            const int col = nf * 8 + cc2;
            float2 m0 = *(float2*)&buf[(mf * 16 + r) * 68 + col];
            float2 m8 = *(float2*)&buf[(mf * 16 + r + 8) * 68 + col];
            float s0 = acc[mf][nf][0] * invt * m0.x;
            float s1 = acc[mf][nf][1] * invt * m0.y;
            float s2 = acc[mf][nf][2] * invt * m8.x;
            float s3 = acc[mf][nf][3] * invt * m8.y;
            ss0 += s0 * s0 + s1 * s1;
            ss8 += s2 * s2 + s3 * s3;
            *(float2*)&buf[(mf * 16 + r) * 68 + col]     = make_float2(s0, s1);
            *(float2*)&buf[(mf * 16 + r + 8) * 68 + col] = make_float2(s2, s3);
        }
        ss0 += __shfl_xor_sync(0xffffffffu, ss0, 1);
        ss0 += __shfl_xor_sync(0xffffffffu, ss0, 2);
        ss8 += __shfl_xor_sync(0xffffffffu, ss8, 1);
        ss8 += __shfl_xor_sync(0xffffffffu, ss8, 2);
        if ((lane & 3) == 0) {
            atomicAdd(&g_rnorm[b * NN + gr0 + mf * 16 + r], ss0);
            atomicAdd(&g_rnorm[b * NN + gr0 + mf * 16 + r + 8], ss8);
        }
    }
    __syncwarp();
    #pragma unroll
    for (int it = 0; it < 16; it++) {
        const int row = it * 2 + (lane >> 4);
        const int col = (lane & 15) * 4;
        float4 v = *(float4*)&buf[row * 68 + col];
        uint32_t lo0, lo1;
        uint32_t hi0 = packsplit(v.x, v.y, lo0);
        uint32_t hi1 = packsplit(v.z, v.w, lo1);
        size_t off = (size_t)(gr0 + row) * NN + gc0 + col;
        *(uint2*)(Sh + off) = make_uint2(hi0, hi1);
        *(uint2*)(Sl + off) = make_uint2(lo0, lo1);
    }
}

// ---------------------------------------------------------------------------
// Kernel 3: out = diag(1/max(||S row||,eps)) * (S @ V)   (3-stage pipeline)
// ---------------------------------------------------------------------------
__global__ __launch_bounds__(256, 2)
void out_kernel(float* __restrict__ out) {
    extern __shared__ __align__(16) uint8_t smem[];
    const int tid = threadIdx.x, wid = tid >> 5, lane = tid & 31;
    const int wm = wid & 3, wn = wid >> 2;
    const int b = blockIdx.z;
    const int iBase = blockIdx.y * 128, eBase = blockIdx.x * 128;
    const uint16_t* Sh = g_Shi + (size_t)b * NN * NN + (size_t)iBase * NN;
    const uint16_t* Sl = g_Slo + (size_t)b * NN * NN + (size_t)iBase * NN;
    const uint16_t* Vh = g_Vhi + (size_t)b * NN * DD + eBase;
    const uint16_t* Vl = g_Vlo + (size_t)b * NN * DD + eBase;
    const uint32_t sb = smem_u32(smem);

    float acc[2][8][4] = {};
    stage_o(sb, Sh, Sl, Vh, Vl, 0, tid);  cpcommit();
    stage_o(sb + STRIDE_O, Sh, Sl, Vh, Vl, 32, tid);  cpcommit();
    int cur = 0, nxt = 2;
    for (int c = 0; c < 64; c++) {
        cpwait<1>(); __syncthreads();
        if (c + 2 < 64) stage_o(sb + nxt * STRIDE_O, Sh, Sl, Vh, Vl, (c + 2) * 32, tid);
        cpcommit();
        compute_chunk<true, 29184, 272>(sb + cur * STRIDE_O, wm, wn, lane, acc);
        cur = (cur == 2) ? 0 : cur + 1;
        nxt = (nxt == 2) ? 0 : nxt + 1;
    }

    // epilogue: bounce + rescale + coalesced f32 stores
    __syncthreads();
    float* buf = (float*)(smem + wid * 8704);
    const int gr0 = iBase + wm * 32, gc0 = eBase + wn * 64;
    const int r = lane >> 2, cc2 = (lane & 3) * 2;
    #pragma unroll
    for (int mf = 0; mf < 2; mf++)
        #pragma unroll
        for (int nf = 0; nf < 8; nf++) {
            const int col = nf * 8 + cc2;
            *(float2*)&buf[(mf * 16 + r) * 68 + col] =
                make_float2(acc[mf][nf][0], acc[mf][nf][1]);
            *(float2*)&buf[(mf * 16 + r + 8) * 68 + col] =
                make_float2(acc[mf][nf][2], acc[mf][nf][3]);
        }
    __syncwarp();
    #pragma unroll
    for (int it = 0; it < 16; it++) {
        const int row = it * 2 + (lane >> 4);
        const int col = (lane & 15) * 4;
        const int gi = gr0 + row;
        float4 v = *(float4*)&buf[row * 68 + col];
        float inv = 1.0f / fmaxf(sqrtf(g_rnorm[b * NN + gi]), NEPS);
        v.x *= inv; v.y *= inv; v.z *= inv; v.w *= inv;
        *(float4*)(out + ((size_t)b * NN + gi) * DD + gc0 + col) = v;
    }
}

// ---------------------------------------------------------------------------
extern "C" void kernel_launch(void* const* d_in, const int* in_sizes, int n_in,
                              void* d_out, int out_size) {
    const float* X    = (const float*)d_in[0];
    const float* mask = (const float*)d_in[1];
    const float* W    = (const float*)d_in[2];
    const float* bias = (const float*)d_in[3];
    float* out = (float*)d_out;

    static int attr_done = 0;
    if (!attr_done) {
        cudaFuncSetAttribute(vproj_kernel,  cudaFuncAttributeMaxDynamicSharedMemorySize, 2 * STRIDE_F);
        cudaFuncSetAttribute(scores_kernel, cudaFuncAttributeMaxDynamicSharedMemorySize, 2 * STRIDE_F);
        cudaFuncSetAttribute(out_kernel,    cudaFuncAttributeMaxDynamicSharedMemorySize, 3 * STRIDE_O);
        attr_done = 1;
    }

    const int NSPLIT = (MM * DD + DD * DD) / 4;
    split_kernel<<<(NSPLIT + 255) / 256, 256>>>(X, W);
    vproj_kernel<<<dim3(4, 128), 256, 2 * STRIDE_F>>>(bias);
    scores_kernel<<<dim3(16, 16, 8), 256, 2 * STRIDE_F>>>(mask);
    out_kernel<<<dim3(4, 16, 8), 256, 3 * STRIDE_O>>>(out);
}

// round 6
// speedup vs baseline: 1.2486x; 1.0111x over previous
#include <cuda_runtime.h>
#include <cuda_bf16.h>
#include <math.h>
#include <stdint.h>

#define BB 8
#define NN 2048
#define DD 512
#define MM (BB * NN)
#define NEPS 1e-5f

// Scratch (__device__ globals — allocation-free per harness rules)
__device__ uint16_t g_Xhi[(size_t)MM * DD];
__device__ uint16_t g_Xlo[(size_t)MM * DD];
__device__ uint16_t g_Whi[(size_t)DD * DD];
__device__ uint16_t g_Wlo[(size_t)DD * DD];
__device__ uint16_t g_Shi[(size_t)BB * NN * NN];
__device__ uint16_t g_Slo[(size_t)BB * NN * NN];
__device__ uint16_t g_Vhi[(size_t)MM * DD];
__device__ uint16_t g_Vlo[(size_t)MM * DD];
__device__ float    g_rnorm[MM];

// ---------------------------------------------------------------------------
// helpers
// ---------------------------------------------------------------------------
__device__ __forceinline__ uint32_t smem_u32(const void* p) {
    uint32_t a;
    asm("{ .reg .u64 t; cvta.to.shared.u64 t, %1; cvt.u32.u64 %0, t; }"
        : "=r"(a) : "l"(p));
    return a;
}
__device__ __forceinline__ void cp16(uint32_t d, const void* g) {
    asm volatile("cp.async.cg.shared.global [%0], [%1], 16;" :: "r"(d), "l"(g));
}
__device__ __forceinline__ void cpcommit() {
    asm volatile("cp.async.commit_group;" ::: "memory");
}
template <int N> __device__ __forceinline__ void cpwait() {
    asm volatile("cp.async.wait_group %0;" :: "n"(N) : "memory");
}
__device__ __forceinline__ void ldsm_x4(uint32_t* r, uint32_t a) {
    asm volatile("ldmatrix.sync.aligned.m8n8.x4.shared.b16 {%0,%1,%2,%3}, [%4];"
                 : "=r"(r[0]), "=r"(r[1]), "=r"(r[2]), "=r"(r[3]) : "r"(a));
}
__device__ __forceinline__ void ldsm_x4t(uint32_t* r, uint32_t a) {
    asm volatile("ldmatrix.sync.aligned.m8n8.x4.trans.shared.b16 {%0,%1,%2,%3}, [%4];"
                 : "=r"(r[0]), "=r"(r[1]), "=r"(r[2]), "=r"(r[3]) : "r"(a));
}
__device__ __forceinline__ void mma16816(float* d, const uint32_t* a, const uint32_t* b) {
    asm volatile(
        "mma.sync.aligned.m16n8k16.row.col.f32.bf16.bf16.f32 "
        "{%0,%1,%2,%3}, {%4,%5,%6,%7}, {%8,%9}, {%0,%1,%2,%3};"
        : "+f"(d[0]), "+f"(d[1]), "+f"(d[2]), "+f"(d[3])
        : "r"(a[0]), "r"(a[1]), "r"(a[2]), "r"(a[3]), "r"(b[0]), "r"(b[1]));
}
__device__ __forceinline__ uint32_t packsplit(float x0, float x1, uint32_t& lo) {
    uint32_t h;
    asm("cvt.rn.bf16x2.f32 %0, %1, %2;" : "=r"(h) : "f"(x1), "f"(x0));
    float r0 = x0 - __uint_as_float(h << 16);
    float r1 = x1 - __uint_as_float(h & 0xffff0000u);
    asm("cvt.rn.bf16x2.f32 %0, %1, %2;" : "=r"(lo) : "f"(r1), "f"(r0));
    return h;
}
__device__ __forceinline__ void split4(float4 x, uint2& hi, uint2& lo) {
    uint32_t l0, l1;
    uint32_t h0 = packsplit(x.x, x.y, l0);
    uint32_t h1 = packsplit(x.z, x.w, l1);
    hi = make_uint2(h0, h1);
    lo = make_uint2(l0, l1);
}

// ---------------------------------------------------------------------------
// compute one K=32 chunk: acc[2][8][4] += A(128x32) * B^T, bf16x3 products.
// MMA order is product-major / accumulator-interleaved: per p, 4 independent
// accs get hh then hl then lh -> same-acc dependency distance 4 (was 1).
// SMEM stage layout: A hi @0 (pitch 80), A lo @10240, B hi @20480 (pitch BP), B lo @BLO
// ---------------------------------------------------------------------------
template <bool BT, int BLO, int BP>
__device__ __forceinline__ void compute_chunk(uint32_t sb, int wm, int wn, int lane,
                                              float acc[2][8][4]) {
    #pragma unroll
    for (int s = 0; s < 2; s++) {
        uint32_t Ah[2][4], Al[2][4];
        uint32_t aaddr = sb + (uint32_t)((wm * 32 + (lane & 15)) * 80
                                         + (s * 16 + (lane >> 4) * 8) * 2);
        ldsm_x4(Ah[0], aaddr);
        ldsm_x4(Ah[1], aaddr + 16 * 80);
        ldsm_x4(Al[0], aaddr + 10240);
        ldsm_x4(Al[1], aaddr + 10240 + 16 * 80);

        #pragma unroll
        for (int p = 0; p < 4; p++) {
            uint32_t rh[4], rl[4], baddr;
            if (!BT) {
                int n  = wn * 64 + p * 16 + (lane >> 4) * 8 + (lane & 7);
                int kc = s * 16 + ((lane >> 3) & 1) * 8;
                baddr = sb + 20480u + (uint32_t)(n * BP + kc * 2);
                ldsm_x4(rh, baddr);
                ldsm_x4(rl, baddr + (uint32_t)(BLO - 20480));
            } else {
                int k = s * 16 + (lane & 7) + ((lane >> 3) & 1) * 8;
                int n = wn * 64 + p * 16 + (lane >> 4) * 8;
                baddr = sb + 20480u + (uint32_t)(k * BP + n * 2);
                ldsm_x4t(rh, baddr);
                ldsm_x4t(rl, baddr + (uint32_t)(BLO - 20480));
            }
            // hh wave (4 independent accumulators)
            mma16816(acc[0][2*p],   Ah[0], &rh[0]);
            mma16816(acc[1][2*p],   Ah[1], &rh[0]);
            mma16816(acc[0][2*p+1], Ah[0], &rh[2]);
            mma16816(acc[1][2*p+1], Ah[1], &rh[2]);
            // hl wave
            mma16816(acc[0][2*p],   Ah[0], &rl[0]);
            mma16816(acc[1][2*p],   Ah[1], &rl[0]);
            mma16816(acc[0][2*p+1], Ah[0], &rl[2]);
            mma16816(acc[1][2*p+1], Ah[1], &rl[2]);
            // lh wave
            mma16816(acc[0][2*p],   Al[0], &rh[0]);
            mma16816(acc[1][2*p],   Al[1], &rh[0]);
            mma16816(acc[0][2*p+1], Al[0], &rh[2]);
            mma16816(acc[1][2*p+1], Al[1], &rh[2]);
        }
    }
}

#define STRIDE_F 40960
#define STRIDE_O 37888

// cp.async stage: A[128 x 32 bf16, ld=512] hi/lo + B same (pitch 80)
__device__ __forceinline__ void stage_f(uint32_t st,
                                        const uint16_t* __restrict__ Ah,
                                        const uint16_t* __restrict__ Al,
                                        const uint16_t* __restrict__ Bh,
                                        const uint16_t* __restrict__ Bl,
                                        int kc, int tid) {
    const uint16_t* srcs[4] = {Ah, Al, Bh, Bl};
    #pragma unroll
    for (int q = 0; q < 8; q++) {
        const int arr = q >> 1;
        const int row = (q & 1) * 64 + (tid >> 2);
        const int seg = tid & 3;
        cp16(st + arr * 10240u + row * 80u + seg * 16u,
             srcs[arr] + (size_t)row * DD + kc + seg * 8);
    }
}

// cp.async stage for out: S[128 x 32, ld=2048] hi/lo (pitch 80) + V[32 x 128, ld=512] hi/lo (pitch 272)
__device__ __forceinline__ void stage_o(uint32_t st,
                                        const uint16_t* __restrict__ Sh,
                                        const uint16_t* __restrict__ Sl,
                                        const uint16_t* __restrict__ Vh,
                                        const uint16_t* __restrict__ Vl,
                                        int kc, int tid) {
    #pragma unroll
    for (int q = 0; q < 4; q++) {
        const int arr = q >> 1;
        const int row = (q & 1) * 64 + (tid >> 2);
        const int seg = tid & 3;
        const uint16_t* s = arr ? Sl : Sh;
        cp16(st + arr * 10240u + row * 80u + seg * 16u,
             s + (size_t)row * NN + kc + seg * 8);
    }
    #pragma unroll
    for (int q = 4; q < 8; q++) {
        const int lo  = (q >= 6);
        const int row = (q & 1) * 16 + (tid >> 4);
        const int seg = tid & 15;
        const uint16_t* s = lo ? Vl : Vh;
        cp16(st + 20480u + lo * 8704u + row * 272u + seg * 16u,
             s + (size_t)(kc + row) * DD + seg * 8);
    }
}

// ---------------------------------------------------------------------------
// prologue: split X and W to bf16 hi/lo
// ---------------------------------------------------------------------------
__global__ __launch_bounds__(256) void split_kernel(const float* __restrict__ X,
                                                    const float* __restrict__ W) {
    const size_t NX = (size_t)MM * DD / 4;
    const size_t NW = (size_t)DD * DD / 4;
    size_t i = (size_t)blockIdx.x * 256 + threadIdx.x;
    if (i < NX) {
        float4 x = ((const float4*)X)[i];
        uint2 hi, lo; split4(x, hi, lo);
        *(uint2*)(g_Xhi + i * 4) = hi;
        *(uint2*)(g_Xlo + i * 4) = lo;
    } else if (i < NX + NW) {
        size_t j = i - NX;
        float4 x = ((const float4*)W)[j];
        uint2 hi, lo; split4(x, hi, lo);
        *(uint2*)(g_Whi + j * 4) = hi;
        *(uint2*)(g_Wlo + j * 4) = lo;
    }
    if (i < MM) g_rnorm[i] = 0.0f;
}

// ---------------------------------------------------------------------------
// Kernel 1: V = elu(X @ W^T + b) -> g_Vhi/g_Vlo [m][e]   (2-stage pipeline)
// ---------------------------------------------------------------------------
__global__ __launch_bounds__(256, 2)
void vproj_kernel(const float* __restrict__ bias) {
    extern __shared__ __align__(16) uint8_t smem[];
    const int tid = threadIdx.x, wid = tid >> 5, lane = tid & 31;
    const int wm = wid & 3, wn = wid >> 2;
    const int eBase = blockIdx.x * 128, mBase = blockIdx.y * 128;
    const uint16_t* Ah = g_Xhi + (size_t)mBase * DD;
    const uint16_t* Al = g_Xlo + (size_t)mBase * DD;
    const uint16_t* Bh = g_Whi + (size_t)eBase * DD;
    const uint16_t* Bl = g_Wlo + (size_t)eBase * DD;
    const uint32_t sb = smem_u32(smem);

    float acc[2][8][4] = {};
    stage_f(sb, Ah, Al, Bh, Bl, 0, tid);  cpcommit();
    for (int c = 0; c < 16; c++) {
        cpwait<0>(); __syncthreads();
        if (c + 1 < 16)
            stage_f(sb + ((c + 1) & 1) * STRIDE_F, Ah, Al, Bh, Bl, (c + 1) * 32, tid);
        cpcommit();
        compute_chunk<false, 30720, 80>(sb + (c & 1) * STRIDE_F, wm, wn, lane, acc);
    }

    // epilogue: bias+elu -> per-warp bounce -> coalesced hi/lo stores
    __syncthreads();
    float* buf = (float*)(smem + wid * 8704);
    const int gr0 = mBase + wm * 32, gc0 = eBase + wn * 64;
    const int r = lane >> 2, cc2 = (lane & 3) * 2;
    #pragma unroll
    for (int mf = 0; mf < 2; mf++)
        #pragma unroll
        for (int nf = 0; nf < 8; nf++) {
            const int col = nf * 8 + cc2;
            float2 bv = *(const float2*)(bias + gc0 + col);
            float v0 = acc[mf][nf][0] + bv.x;
            float v1 = acc[mf][nf][1] + bv.y;
            float v2 = acc[mf][nf][2] + bv.x;
            float v3 = acc[mf][nf][3] + bv.y;
            v0 = v0 > 0.0f ? v0 : expm1f(v0);
            v1 = v1 > 0.0f ? v1 : expm1f(v1);
            v2 = v2 > 0.0f ? v2 : expm1f(v2);
            v3 = v3 > 0.0f ? v3 : expm1f(v3);
            *(float2*)&buf[(mf * 16 + r) * 68 + col]     = make_float2(v0, v1);
            *(float2*)&buf[(mf * 16 + r + 8) * 68 + col] = make_float2(v2, v3);
        }
    __syncwarp();
    #pragma unroll
    for (int it = 0; it < 16; it++) {
        const int row = it * 2 + (lane >> 4);
        const int col = (lane & 15) * 4;
        float4 v = *(float4*)&buf[row * 68 + col];
        uint32_t lo0, lo1;
        uint32_t hi0 = packsplit(v.x, v.y, lo0);
        uint32_t hi1 = packsplit(v.z, v.w, lo1);
        size_t off = (size_t)(gr0 + row) * DD + gc0 + col;
        *(uint2*)(g_Vhi + off) = make_uint2(hi0, hi1);
        *(uint2*)(g_Vlo + off) = make_uint2(lo0, lo1);
    }
}

// ---------------------------------------------------------------------------
// Kernel 2: S = (X X^T / sqrt(D)) * mask -> g_Shi/g_Slo + rnorm atomics
// ---------------------------------------------------------------------------
__global__ __launch_bounds__(256, 2)
void scores_kernel(const float* __restrict__ mask) {
    extern __shared__ __align__(16) uint8_t smem[];
    const int tid = threadIdx.x, wid = tid >> 5, lane = tid & 31;
    const int wm = wid & 3, wn = wid >> 2;
    const int b = blockIdx.z;
    const int iBase = blockIdx.y * 128, jBase = blockIdx.x * 128;
    const uint16_t* Ah = g_Xhi + (size_t)(b * NN + iBase) * DD;
    const uint16_t* Al = g_Xlo + (size_t)(b * NN + iBase) * DD;
    const uint16_t* Bh = g_Xhi + (size_t)(b * NN + jBase) * DD;
    const uint16_t* Bl = g_Xlo + (size_t)(b * NN + jBase) * DD;
    const float* Mb = mask + (size_t)b * NN * NN;
    uint16_t* Sh = g_Shi + (size_t)b * NN * NN;
    uint16_t* Sl = g_Slo + (size_t)b * NN * NN;
    const uint32_t sb = smem_u32(smem);

    float acc[2][8][4] = {};
    stage_f(sb, Ah, Al, Bh, Bl, 0, tid);  cpcommit();
    for (int c = 0; c < 16; c++) {
        cpwait<0>(); __syncthreads();
        if (c + 1 < 16)
            stage_f(sb + ((c + 1) & 1) * STRIDE_F, Ah, Al, Bh, Bl, (c + 1) * 32, tid);
        cpcommit();
        compute_chunk<false, 30720, 80>(sb + (c & 1) * STRIDE_F, wm, wn, lane, acc);
    }

    // epilogue
    __syncthreads();
    const uint32_t bufa = sb + wid * 8704u;
    float* buf = (float*)(smem + wid * 8704);
    const int gr0 = iBase + wm * 32, gc0 = jBase + wn * 64;
    #pragma unroll
    for (int q = 0; q < 16; q++) {
        const int idx = q * 32 + lane;
        const int row = idx >> 4, seg = idx & 15;
        cp16(bufa + row * 272u + seg * 16u,
             Mb + (size_t)(gr0 + row) * NN + gc0 + seg * 4);
    }
    cpcommit(); cpwait<0>(); __syncwarp();

    const float invt = 0.044194173824159216f;  // 1/sqrt(512)
    const int r = lane >> 2, cc2 = (lane & 3) * 2;
    #pragma unroll
    for (int mf = 0; mf < 2; mf++) {
        float ss0 = 0.0f, ss8 = 0.0f;
        #pragma unroll
        for (int nf = 0; nf < 8; nf++) {
            const int col = nf * 8 + cc2;
            float2 m0 = *(float2*)&buf[(mf * 16 + r) * 68 + col];
            float2 m8 = *(float2*)&buf[(mf * 16 + r + 8) * 68 + col];
            float s0 = acc[mf][nf][0] * invt * m0.x;
            float s1 = acc[mf][nf][1] * invt * m0.y;
            float s2 = acc[mf][nf][2] * invt * m8.x;
            float s3 = acc[mf][nf][3] * invt * m8.y;
            ss0 += s0 * s0 + s1 * s1;
            ss8 += s2 * s2 + s3 * s3;
            *(float2*)&buf[(mf * 16 + r) * 68 + col]     = make_float2(s0, s1);
            *(float2*)&buf[(mf * 16 + r + 8) * 68 + col] = make_float2(s2, s3);
        }
        ss0 += __shfl_xor_sync(0xffffffffu, ss0, 1);
        ss0 += __shfl_xor_sync(0xffffffffu, ss0, 2);
        ss8 += __shfl_xor_sync(0xffffffffu, ss8, 1);
        ss8 += __shfl_xor_sync(0xffffffffu, ss8, 2);
        if ((lane & 3) == 0) {
            atomicAdd(&g_rnorm[b * NN + gr0 + mf * 16 + r], ss0);
            atomicAdd(&g_rnorm[b * NN + gr0 + mf * 16 + r + 8], ss8);
        }
    }
    __syncwarp();
    #pragma unroll
    for (int it = 0; it < 16; it++) {
        const int row = it * 2 + (lane >> 4);
        const int col = (lane & 15) * 4;
        float4 v = *(float4*)&buf[row * 68 + col];
        uint32_t lo0, lo1;
        uint32_t hi0 = packsplit(v.x, v.y, lo0);
        uint32_t hi1 = packsplit(v.z, v.w, lo1);
        size_t off = (size_t)(gr0 + row) * NN + gc0 + col;
        *(uint2*)(Sh + off) = make_uint2(hi0, hi1);
        *(uint2*)(Sl + off) = make_uint2(lo0, lo1);
    }
}

// ---------------------------------------------------------------------------
// Kernel 3: out = diag(1/max(||S row||,eps)) * (S @ V)   (3-stage pipeline)
// ---------------------------------------------------------------------------
__global__ __launch_bounds__(256, 2)
void out_kernel(float* __restrict__ out) {
    extern __shared__ __align__(16) uint8_t smem[];
    const int tid = threadIdx.x, wid = tid >> 5, lane = tid & 31;
    const int wm = wid & 3, wn = wid >> 2;
    const int b = blockIdx.z;
    const int iBase = blockIdx.y * 128, eBase = blockIdx.x * 128;
    const uint16_t* Sh = g_Shi + (size_t)b * NN * NN + (size_t)iBase * NN;
    const uint16_t* Sl = g_Slo + (size_t)b * NN * NN + (size_t)iBase * NN;
    const uint16_t* Vh = g_Vhi + (size_t)b * NN * DD + eBase;
    const uint16_t* Vl = g_Vlo + (size_t)b * NN * DD + eBase;
    const uint32_t sb = smem_u32(smem);

    float acc[2][8][4] = {};
    stage_o(sb, Sh, Sl, Vh, Vl, 0, tid);  cpcommit();
    stage_o(sb + STRIDE_O, Sh, Sl, Vh, Vl, 32, tid);  cpcommit();
    int cur = 0, nxt = 2;
    for (int c = 0; c < 64; c++) {
        cpwait<1>(); __syncthreads();
        if (c + 2 < 64) stage_o(sb + nxt * STRIDE_O, Sh, Sl, Vh, Vl, (c + 2) * 32, tid);
        cpcommit();
        compute_chunk<true, 29184, 272>(sb + cur * STRIDE_O, wm, wn, lane, acc);
        cur = (cur == 2) ? 0 : cur + 1;
        nxt = (nxt == 2) ? 0 : nxt + 1;
    }

    // epilogue: bounce + rescale + coalesced f32 stores
    __syncthreads();
    float* buf = (float*)(smem + wid * 8704);
    const int gr0 = iBase + wm * 32, gc0 = eBase + wn * 64;
    const int r = lane >> 2, cc2 = (lane & 3) * 2;
    #pragma unroll
    for (int mf = 0; mf < 2; mf++)
        #pragma unroll
        for (int nf = 0; nf < 8; nf++) {
            const int col = nf * 8 + cc2;
            *(float2*)&buf[(mf * 16 + r) * 68 + col] =
                make_float2(acc[mf][nf][0], acc[mf][nf][1]);
            *(float2*)&buf[(mf * 16 + r + 8) * 68 + col] =
                make_float2(acc[mf][nf][2], acc[mf][nf][3]);
        }
    __syncwarp();
    #pragma unroll
    for (int it = 0; it < 16; it++) {
        const int row = it * 2 + (lane >> 4);
        const int col = (lane & 15) * 4;
        const int gi = gr0 + row;
        float4 v = *(float4*)&buf[row * 68 + col];
        float inv = 1.0f / fmaxf(sqrtf(g_rnorm[b * NN + gi]), NEPS);
        v.x *= inv; v.y *= inv; v.z *= inv; v.w *= inv;
        *(float4*)(out + ((size_t)b * NN + gi) * DD + gc0 + col) = v;
    }
}

// ---------------------------------------------------------------------------
extern "C" void kernel_launch(void* const* d_in, const int* in_sizes, int n_in,
                              void* d_out, int out_size) {
    const float* X    = (const float*)d_in[0];
    const float* mask = (const float*)d_in[1];
    const float* W    = (const float*)d_in[2];
    const float* bias = (const float*)d_in[3];
    float* out = (float*)d_out;

    static int attr_done = 0;
    if (!attr_done) {
        cudaFuncSetAttribute(vproj_kernel,  cudaFuncAttributeMaxDynamicSharedMemorySize, 2 * STRIDE_F);
        cudaFuncSetAttribute(scores_kernel, cudaFuncAttributeMaxDynamicSharedMemorySize, 2 * STRIDE_F);
        cudaFuncSetAttribute(out_kernel,    cudaFuncAttributeMaxDynamicSharedMemorySize, 3 * STRIDE_O);
        attr_done = 1;
    }

    const int NSPLIT = (MM * DD + DD * DD) / 4;
    split_kernel<<<(NSPLIT + 255) / 256, 256>>>(X, W);
    vproj_kernel<<<dim3(4, 128), 256, 2 * STRIDE_F>>>(bias);
    scores_kernel<<<dim3(16, 16, 8), 256, 2 * STRIDE_F>>>(mask);
    out_kernel<<<dim3(4, 16, 8), 256, 3 * STRIDE_O>>>(out);
}

// round 7
// speedup vs baseline: 1.4760x; 1.1821x over previous
#include <cuda_runtime.h>
#include <cuda_bf16.h>
#include <math.h>
#include <stdint.h>

#define BB 8
#define NN 2048
#define DD 512
#define MM (BB * NN)
#define NEPS 1e-5f

// Scratch (__device__ globals — allocation-free per harness rules)
__device__ uint16_t g_Xhi[(size_t)MM * DD];
__device__ uint16_t g_Xlo[(size_t)MM * DD];
__device__ uint16_t g_Whi[(size_t)DD * DD];
__device__ uint16_t g_Wlo[(size_t)DD * DD];
__device__ uint16_t g_Shi[(size_t)BB * NN * NN];
__device__ uint16_t g_Slo[(size_t)BB * NN * NN];
__device__ uint16_t g_Vhi[(size_t)MM * DD];
__device__ uint16_t g_Vlo[(size_t)MM * DD];
__device__ float    g_rnorm[MM];

// ---------------------------------------------------------------------------
// helpers
// ---------------------------------------------------------------------------
__device__ __forceinline__ uint32_t smem_u32(const void* p) {
    uint32_t a;
    asm("{ .reg .u64 t; cvta.to.shared.u64 t, %1; cvt.u32.u64 %0, t; }"
        : "=r"(a) : "l"(p));
    return a;
}
__device__ __forceinline__ void cp16(uint32_t d, const void* g) {
    asm volatile("cp.async.cg.shared.global [%0], [%1], 16;" :: "r"(d), "l"(g));
}
__device__ __forceinline__ void cpcommit() {
    asm volatile("cp.async.commit_group;" ::: "memory");
}
template <int N> __device__ __forceinline__ void cpwait() {
    asm volatile("cp.async.wait_group %0;" :: "n"(N) : "memory");
}
__device__ __forceinline__ void ldsm_x4(uint32_t* r, uint32_t a) {
    asm volatile("ldmatrix.sync.aligned.m8n8.x4.shared.b16 {%0,%1,%2,%3}, [%4];"
                 : "=r"(r[0]), "=r"(r[1]), "=r"(r[2]), "=r"(r[3]) : "r"(a));
}
__device__ __forceinline__ void ldsm_x4t(uint32_t* r, uint32_t a) {
    asm volatile("ldmatrix.sync.aligned.m8n8.x4.trans.shared.b16 {%0,%1,%2,%3}, [%4];"
                 : "=r"(r[0]), "=r"(r[1]), "=r"(r[2]), "=r"(r[3]) : "r"(a));
}
__device__ __forceinline__ void mma16816(float* d, const uint32_t* a, const uint32_t* b) {
    asm volatile(
        "mma.sync.aligned.m16n8k16.row.col.f32.bf16.bf16.f32 "
        "{%0,%1,%2,%3}, {%4,%5,%6,%7}, {%8,%9}, {%0,%1,%2,%3};"
        : "+f"(d[0]), "+f"(d[1]), "+f"(d[2]), "+f"(d[3])
        : "r"(a[0]), "r"(a[1]), "r"(a[2]), "r"(a[3]), "r"(b[0]), "r"(b[1]));
}
__device__ __forceinline__ uint32_t packsplit(float x0, float x1, uint32_t& lo) {
    uint32_t h;
    asm("cvt.rn.bf16x2.f32 %0, %1, %2;" : "=r"(h) : "f"(x1), "f"(x0));
    float r0 = x0 - __uint_as_float(h << 16);
    float r1 = x1 - __uint_as_float(h & 0xffff0000u);
    asm("cvt.rn.bf16x2.f32 %0, %1, %2;" : "=r"(lo) : "f"(r1), "f"(r0));
    return h;
}
__device__ __forceinline__ void split4(float4 x, uint2& hi, uint2& lo) {
    uint32_t l0, l1;
    uint32_t h0 = packsplit(x.x, x.y, l0);
    uint32_t h1 = packsplit(x.z, x.w, l1);
    hi = make_uint2(h0, h1);
    lo = make_uint2(l0, l1);
}

// ---------------------------------------------------------------------------
// compute one K=32 chunk: acc[2][8][4] += A(128x32) * B^T, bf16x3 products.
// SMEM stage layout: A hi @0 (pitch 80), A lo @10240, B hi @20480 (pitch BP), B lo @BLO
// ---------------------------------------------------------------------------
template <bool BT, int BLO, int BP>
__device__ __forceinline__ void compute_chunk(uint32_t sb, int wm, int wn, int lane,
                                              float acc[2][8][4]) {
    #pragma unroll
    for (int s = 0; s < 2; s++) {
        uint32_t Ah[2][4], Al[2][4];
        uint32_t aaddr = sb + (uint32_t)((wm * 32 + (lane & 15)) * 80
                                         + (s * 16 + (lane >> 4) * 8) * 2);
        ldsm_x4(Ah[0], aaddr);
        ldsm_x4(Ah[1], aaddr + 16 * 80);
        ldsm_x4(Al[0], aaddr + 10240);
        ldsm_x4(Al[1], aaddr + 10240 + 16 * 80);

        #pragma unroll
        for (int p = 0; p < 4; p++) {
            uint32_t rh[4], rl[4], baddr;
            if (!BT) {
                int n  = wn * 64 + p * 16 + (lane >> 4) * 8 + (lane & 7);
                int kc = s * 16 + ((lane >> 3) & 1) * 8;
                baddr = sb + 20480u + (uint32_t)(n * BP + kc * 2);
                ldsm_x4(rh, baddr);
                ldsm_x4(rl, baddr + (uint32_t)(BLO - 20480));
            } else {
                int k = s * 16 + (lane & 7) + ((lane >> 3) & 1) * 8;
                int n = wn * 64 + p * 16 + (lane >> 4) * 8;
                baddr = sb + 20480u + (uint32_t)(k * BP + n * 2);
                ldsm_x4t(rh, baddr);
                ldsm_x4t(rl, baddr + (uint32_t)(BLO - 20480));
            }
            mma16816(acc[0][2*p],   Ah[0], &rh[0]);
            mma16816(acc[1][2*p],   Ah[1], &rh[0]);
            mma16816(acc[0][2*p+1], Ah[0], &rh[2]);
            mma16816(acc[1][2*p+1], Ah[1], &rh[2]);
            mma16816(acc[0][2*p],   Ah[0], &rl[0]);
            mma16816(acc[1][2*p],   Ah[1], &rl[0]);
            mma16816(acc[0][2*p+1], Ah[0], &rl[2]);
            mma16816(acc[1][2*p+1], Ah[1], &rl[2]);
            mma16816(acc[0][2*p],   Al[0], &rh[0]);
            mma16816(acc[1][2*p],   Al[1], &rh[0]);
            mma16816(acc[0][2*p+1], Al[0], &rh[2]);
            mma16816(acc[1][2*p+1], Al[1], &rh[2]);
        }
    }
}

#define STRIDE_F 40960
#define STRIDE_O 37888

// cp.async stage: A[128 x 32 bf16, ld=512] hi/lo + B same (pitch 80)
__device__ __forceinline__ void stage_f(uint32_t st,
                                        const uint16_t* __restrict__ Ah,
                                        const uint16_t* __restrict__ Al,
                                        const uint16_t* __restrict__ Bh,
                                        const uint16_t* __restrict__ Bl,
                                        int kc, int tid) {
    const uint16_t* srcs[4] = {Ah, Al, Bh, Bl};
    #pragma unroll
    for (int q = 0; q < 8; q++) {
        const int arr = q >> 1;
        const int row = (q & 1) * 64 + (tid >> 2);
        const int seg = tid & 3;
        cp16(st + arr * 10240u + row * 80u + seg * 16u,
             srcs[arr] + (size_t)row * DD + kc + seg * 8);
    }
}

// cp.async stage for out: S[128 x 32, ld=2048] hi/lo (pitch 80) + V[32 x 128, ld=512] hi/lo (pitch 272)
__device__ __forceinline__ void stage_o(uint32_t st,
                                        const uint16_t* __restrict__ Sh,
                                        const uint16_t* __restrict__ Sl,
                                        const uint16_t* __restrict__ Vh,
                                        const uint16_t* __restrict__ Vl,
                                        int kc, int tid) {
    #pragma unroll
    for (int q = 0; q < 4; q++) {
        const int arr = q >> 1;
        const int row = (q & 1) * 64 + (tid >> 2);
        const int seg = tid & 3;
        const uint16_t* s = arr ? Sl : Sh;
        cp16(st + arr * 10240u + row * 80u + seg * 16u,
             s + (size_t)row * NN + kc + seg * 8);
    }
    #pragma unroll
    for (int q = 4; q < 8; q++) {
        const int lo  = (q >= 6);
        const int row = (q & 1) * 16 + (tid >> 4);
        const int seg = tid & 15;
        const uint16_t* s = lo ? Vl : Vh;
        cp16(st + 20480u + lo * 8704u + row * 272u + seg * 16u,
             s + (size_t)(kc + row) * DD + seg * 8);
    }
}

// ---------------------------------------------------------------------------
// prologue: split X and W to bf16 hi/lo
// ---------------------------------------------------------------------------
__global__ __launch_bounds__(256) void split_kernel(const float* __restrict__ X,
                                                    const float* __restrict__ W) {
    const size_t NX = (size_t)MM * DD / 4;
    const size_t NW = (size_t)DD * DD / 4;
    size_t i = (size_t)blockIdx.x * 256 + threadIdx.x;
    if (i < NX) {
        float4 x = ((const float4*)X)[i];
        uint2 hi, lo; split4(x, hi, lo);
        *(uint2*)(g_Xhi + i * 4) = hi;
        *(uint2*)(g_Xlo + i * 4) = lo;
    } else if (i < NX + NW) {
        size_t j = i - NX;
        float4 x = ((const float4*)W)[j];
        uint2 hi, lo; split4(x, hi, lo);
        *(uint2*)(g_Whi + j * 4) = hi;
        *(uint2*)(g_Wlo + j * 4) = lo;
    }
    if (i < MM) g_rnorm[i] = 0.0f;
}

// ---------------------------------------------------------------------------
// Kernel 1: V = elu(X @ W^T + b) -> g_Vhi/g_Vlo [m][e]   (2-stage pipeline)
// ---------------------------------------------------------------------------
__global__ __launch_bounds__(256, 2)
void vproj_kernel(const float* __restrict__ bias) {
    extern __shared__ __align__(16) uint8_t smem[];
    const int tid = threadIdx.x, wid = tid >> 5, lane = tid & 31;
    const int wm = wid & 3, wn = wid >> 2;
    const int eBase = blockIdx.x * 128, mBase = blockIdx.y * 128;
    const uint16_t* Ah = g_Xhi + (size_t)mBase * DD;
    const uint16_t* Al = g_Xlo + (size_t)mBase * DD;
    const uint16_t* Bh = g_Whi + (size_t)eBase * DD;
    const uint16_t* Bl = g_Wlo + (size_t)eBase * DD;
    const uint32_t sb = smem_u32(smem);

    float acc[2][8][4] = {};
    stage_f(sb, Ah, Al, Bh, Bl, 0, tid);  cpcommit();
    for (int c = 0; c < 16; c++) {
        cpwait<0>(); __syncthreads();
        if (c + 1 < 16)
            stage_f(sb + ((c + 1) & 1) * STRIDE_F, Ah, Al, Bh, Bl, (c + 1) * 32, tid);
        cpcommit();
        compute_chunk<false, 30720, 80>(sb + (c & 1) * STRIDE_F, wm, wn, lane, acc);
    }

    // epilogue: bias+elu -> per-warp bounce -> coalesced hi/lo stores
    __syncthreads();
    float* buf = (float*)(smem + wid * 8704);
    const int gr0 = mBase + wm * 32, gc0 = eBase + wn * 64;
    const int r = lane >> 2, cc2 = (lane & 3) * 2;
    #pragma unroll
    for (int mf = 0; mf < 2; mf++)
        #pragma unroll
        for (int nf = 0; nf < 8; nf++) {
            const int col = nf * 8 + cc2;
            float2 bv = *(const float2*)(bias + gc0 + col);
            float v0 = acc[mf][nf][0] + bv.x;
            float v1 = acc[mf][nf][1] + bv.y;
            float v2 = acc[mf][nf][2] + bv.x;
            float v3 = acc[mf][nf][3] + bv.y;
            v0 = v0 > 0.0f ? v0 : expm1f(v0);
            v1 = v1 > 0.0f ? v1 : expm1f(v1);
            v2 = v2 > 0.0f ? v2 : expm1f(v2);
            v3 = v3 > 0.0f ? v3 : expm1f(v3);
            *(float2*)&buf[(mf * 16 + r) * 68 + col]     = make_float2(v0, v1);
            *(float2*)&buf[(mf * 16 + r + 8) * 68 + col] = make_float2(v2, v3);
        }
    __syncwarp();
    #pragma unroll
    for (int it = 0; it < 16; it++) {
        const int row = it * 2 + (lane >> 4);
        const int col = (lane & 15) * 4;
        float4 v = *(float4*)&buf[row * 68 + col];
        uint32_t lo0, lo1;
        uint32_t hi0 = packsplit(v.x, v.y, lo0);
        uint32_t hi1 = packsplit(v.z, v.w, lo1);
        size_t off = (size_t)(gr0 + row) * DD + gc0 + col;
        *(uint2*)(g_Vhi + off) = make_uint2(hi0, hi1);
        *(uint2*)(g_Vlo + off) = make_uint2(lo0, lo1);
    }
}

// ---------------------------------------------------------------------------
// Kernel 2 (symmetric): S = (X X^T / sqrt(D)) * mask, lower-tri tile pairs.
// grid (136, 1, 8): tile pair t -> (a, b) with a <= b; computes tile
// (iBase=a*128, jBase=b*128) once, emits it straight and (if a != b)
// transposed with the other mask, accumulating rnorm for both row ranges.
// ---------------------------------------------------------------------------
__global__ __launch_bounds__(256, 2)
void scores_kernel(const float* __restrict__ mask) {
    extern __shared__ __align__(16) uint8_t smem[];
    const int tid = threadIdx.x, wid = tid >> 5, lane = tid & 31;
    const int wm = wid & 3, wn = wid >> 2;
    const int b = blockIdx.z;

    int t = blockIdx.x;
    int tb = (int)((sqrtf(8.0f * t + 1.0f) - 1.0f) * 0.5f);
    while ((tb + 1) * (tb + 2) / 2 <= t) tb++;
    while (tb * (tb + 1) / 2 > t) tb--;
    const int ta = t - tb * (tb + 1) / 2;   // ta <= tb
    const int iBase = ta * 128, jBase = tb * 128;

    const uint16_t* Ah = g_Xhi + (size_t)(b * NN + iBase) * DD;
    const uint16_t* Al = g_Xlo + (size_t)(b * NN + iBase) * DD;
    const uint16_t* Bh = g_Xhi + (size_t)(b * NN + jBase) * DD;
    const uint16_t* Bl = g_Xlo + (size_t)(b * NN + jBase) * DD;
    const float* Mb = mask + (size_t)b * NN * NN;
    uint16_t* Sh = g_Shi + (size_t)b * NN * NN;
    uint16_t* Sl = g_Slo + (size_t)b * NN * NN;
    const uint32_t sb = smem_u32(smem);

    float acc[2][8][4] = {};
    stage_f(sb, Ah, Al, Bh, Bl, 0, tid);  cpcommit();
    for (int c = 0; c < 16; c++) {
        cpwait<0>(); __syncthreads();
        if (c + 1 < 16)
            stage_f(sb + ((c + 1) & 1) * STRIDE_F, Ah, Al, Bh, Bl, (c + 1) * 32, tid);
        cpcommit();
        compute_chunk<false, 30720, 80>(sb + (c & 1) * STRIDE_F, wm, wn, lane, acc);
    }

    // epilogue: raw*invt into per-warp bounce buffer (32 x 64, pitch 68 floats)
    __syncthreads();
    float* buf = (float*)(smem + wid * 8704);
    const int gr0 = iBase + wm * 32, gc0 = jBase + wn * 64;
    const float invt = 0.044194173824159216f;  // 1/sqrt(512)
    {
        const int r = lane >> 2, cc2 = (lane & 3) * 2;
        #pragma unroll
        for (int mf = 0; mf < 2; mf++)
            #pragma unroll
            for (int nf = 0; nf < 8; nf++) {
                const int col = nf * 8 + cc2;
                *(float2*)&buf[(mf * 16 + r) * 68 + col] =
                    make_float2(acc[mf][nf][0] * invt, acc[mf][nf][1] * invt);
                *(float2*)&buf[(mf * 16 + r + 8) * 68 + col] =
                    make_float2(acc[mf][nf][2] * invt, acc[mf][nf][3] * invt);
            }
    }
    __syncwarp();

    // Pass 1: straight orientation (rows i, cols j), mask(i,j), rnorm rows i
    #pragma unroll
    for (int it = 0; it < 16; it++) {
        const int row = it * 2 + (lane >> 4);
        const int col = (lane & 15) * 4;
        const int gi = gr0 + row, gj = gc0 + col;
        float4 m = *(const float4*)(Mb + (size_t)gi * NN + gj);
        float4 v = *(float4*)&buf[row * 68 + col];
        v.x *= m.x; v.y *= m.y; v.z *= m.z; v.w *= m.w;
        float ss = v.x * v.x + v.y * v.y + v.z * v.z + v.w * v.w;
        ss += __shfl_xor_sync(0xffffffffu, ss, 1);
        ss += __shfl_xor_sync(0xffffffffu, ss, 2);
        ss += __shfl_xor_sync(0xffffffffu, ss, 4);
        ss += __shfl_xor_sync(0xffffffffu, ss, 8);
        if ((lane & 15) == 0) atomicAdd(&g_rnorm[b * NN + gi], ss);
        uint32_t lo0, lo1;
        uint32_t hi0 = packsplit(v.x, v.y, lo0);
        uint32_t hi1 = packsplit(v.z, v.w, lo1);
        size_t off = (size_t)gi * NN + gj;
        *(uint2*)(Sh + off) = make_uint2(hi0, hi1);
        *(uint2*)(Sl + off) = make_uint2(lo0, lo1);
    }

    // Pass 2: transposed (rows j, cols i), mask(j,i), rnorm rows j
    if (ta != tb) {
        #pragma unroll
        for (int it = 0; it < 32; it++) {
            const int row2 = it * 2 + (lane >> 4);   // 0..63 (j-local)
            const int col2 = (lane & 15) * 2;        // 0..30 (i-local)
            const int gj2 = gc0 + row2, gi2 = gr0 + col2;
            float2 m = *(const float2*)(Mb + (size_t)gj2 * NN + gi2);
            float s0 = buf[col2 * 68 + row2] * m.x;
            float s1 = buf[(col2 + 1) * 68 + row2] * m.y;
            float ss = s0 * s0 + s1 * s1;
            ss += __shfl_xor_sync(0xffffffffu, ss, 1);
            ss += __shfl_xor_sync(0xffffffffu, ss, 2);
            ss += __shfl_xor_sync(0xffffffffu, ss, 4);
            ss += __shfl_xor_sync(0xffffffffu, ss, 8);
            if ((lane & 15) == 0) atomicAdd(&g_rnorm[b * NN + gj2], ss);
            uint32_t lo0;
            uint32_t hi0 = packsplit(s0, s1, lo0);
            size_t off = (size_t)gj2 * NN + gi2;
            *(uint32_t*)(Sh + off) = hi0;
            *(uint32_t*)(Sl + off) = lo0;
        }
    }
}

// ---------------------------------------------------------------------------
// Kernel 3: out = diag(1/max(||S row||,eps)) * (S @ V)   (3-stage pipeline)
// ---------------------------------------------------------------------------
__global__ __launch_bounds__(256, 2)
void out_kernel(float* __restrict__ out) {
    extern __shared__ __align__(16) uint8_t smem[];
    const int tid = threadIdx.x, wid = tid >> 5, lane = tid & 31;
    const int wm = wid & 3, wn = wid >> 2;
    const int b = blockIdx.z;
    const int iBase = blockIdx.y * 128, eBase = blockIdx.x * 128;
    const uint16_t* Sh = g_Shi + (size_t)b * NN * NN + (size_t)iBase * NN;
    const uint16_t* Sl = g_Slo + (size_t)b * NN * NN + (size_t)iBase * NN;
    const uint16_t* Vh = g_Vhi + (size_t)b * NN * DD + eBase;
    const uint16_t* Vl = g_Vlo + (size_t)b * NN * DD + eBase;
    const uint32_t sb = smem_u32(smem);

    float acc[2][8][4] = {};
    stage_o(sb, Sh, Sl, Vh, Vl, 0, tid);  cpcommit();
    stage_o(sb + STRIDE_O, Sh, Sl, Vh, Vl, 32, tid);  cpcommit();
    int cur = 0, nxt = 2;
    for (int c = 0; c < 64; c++) {
        cpwait<1>(); __syncthreads();
        if (c + 2 < 64) stage_o(sb + nxt * STRIDE_O, Sh, Sl, Vh, Vl, (c + 2) * 32, tid);
        cpcommit();
        compute_chunk<true, 29184, 272>(sb + cur * STRIDE_O, wm, wn, lane, acc);
        cur = (cur == 2) ? 0 : cur + 1;
        nxt = (nxt == 2) ? 0 : nxt + 1;
    }

    // epilogue: bounce + rescale + coalesced f32 stores
    __syncthreads();
    float* buf = (float*)(smem + wid * 8704);
    const int gr0 = iBase + wm * 32, gc0 = eBase + wn * 64;
    const int r = lane >> 2, cc2 = (lane & 3) * 2;
    #pragma unroll
    for (int mf = 0; mf < 2; mf++)
        #pragma unroll
        for (int nf = 0; nf < 8; nf++) {
            const int col = nf * 8 + cc2;
            *(float2*)&buf[(mf * 16 + r) * 68 + col] =
                make_float2(acc[mf][nf][0], acc[mf][nf][1]);
            *(float2*)&buf[(mf * 16 + r + 8) * 68 + col] =
                make_float2(acc[mf][nf][2], acc[mf][nf][3]);
        }
    __syncwarp();
    #pragma unroll
    for (int it = 0; it < 16; it++) {
        const int row = it * 2 + (lane >> 4);
        const int col = (lane & 15) * 4;
        const int gi = gr0 + row;
        float4 v = *(float4*)&buf[row * 68 + col];
        float inv = 1.0f / fmaxf(sqrtf(g_rnorm[b * NN + gi]), NEPS);
        v.x *= inv; v.y *= inv; v.z *= inv; v.w *= inv;
        *(float4*)(out + ((size_t)b * NN + gi) * DD + gc0 + col) = v;
    }
}

// ---------------------------------------------------------------------------
extern "C" void kernel_launch(void* const* d_in, const int* in_sizes, int n_in,
                              void* d_out, int out_size) {
    const float* X    = (const float*)d_in[0];
    const float* mask = (const float*)d_in[1];
    const float* W    = (const float*)d_in[2];
    const float* bias = (const float*)d_in[3];
    float* out = (float*)d_out;

    static int attr_done = 0;
    if (!attr_done) {
        cudaFuncSetAttribute(vproj_kernel,  cudaFuncAttributeMaxDynamicSharedMemorySize, 2 * STRIDE_F);
        cudaFuncSetAttribute(scores_kernel, cudaFuncAttributeMaxDynamicSharedMemorySize, 2 * STRIDE_F);
        cudaFuncSetAttribute(out_kernel,    cudaFuncAttributeMaxDynamicSharedMemorySize, 3 * STRIDE_O);
        attr_done = 1;
    }

    const int NSPLIT = (MM * DD + DD * DD) / 4;
    split_kernel<<<(NSPLIT + 255) / 256, 256>>>(X, W);
    vproj_kernel<<<dim3(4, 128), 256, 2 * STRIDE_F>>>(bias);
    scores_kernel<<<dim3(136, 1, 8), 256, 2 * STRIDE_F>>>(mask);
    out_kernel<<<dim3(4, 16, 8), 256, 3 * STRIDE_O>>>(out);
}

// round 8
// speedup vs baseline: 1.5158x; 1.0270x over previous
#include <cuda_runtime.h>
#include <cuda_bf16.h>
#include <math.h>
#include <stdint.h>

#define BB 8
#define NN 2048
#define DD 512
#define MM (BB * NN)
#define NEPS 1e-5f

// Scratch (__device__ globals — allocation-free per harness rules)
__device__ uint16_t g_Xhi[(size_t)MM * DD];
__device__ uint16_t g_Xlo[(size_t)MM * DD];
__device__ uint16_t g_Whi[(size_t)DD * DD];
__device__ uint16_t g_Wlo[(size_t)DD * DD];
__device__ uint16_t g_Shi[(size_t)BB * NN * NN];
__device__ uint16_t g_Slo[(size_t)BB * NN * NN];
__device__ uint16_t g_Vhi[(size_t)MM * DD];
__device__ uint16_t g_Vlo[(size_t)MM * DD];
__device__ float    g_rnorm[MM];

// ---------------------------------------------------------------------------
// helpers
// ---------------------------------------------------------------------------
__device__ __forceinline__ uint32_t smem_u32(const void* p) {
    uint32_t a;
    asm("{ .reg .u64 t; cvta.to.shared.u64 t, %1; cvt.u32.u64 %0, t; }"
        : "=r"(a) : "l"(p));
    return a;
}
__device__ __forceinline__ void cp16(uint32_t d, const void* g) {
    asm volatile("cp.async.cg.shared.global [%0], [%1], 16;" :: "r"(d), "l"(g));
}
__device__ __forceinline__ void cpcommit() {
    asm volatile("cp.async.commit_group;" ::: "memory");
}
template <int N> __device__ __forceinline__ void cpwait() {
    asm volatile("cp.async.wait_group %0;" :: "n"(N) : "memory");
}
__device__ __forceinline__ void ldsm_x4(uint32_t* r, uint32_t a) {
    asm volatile("ldmatrix.sync.aligned.m8n8.x4.shared.b16 {%0,%1,%2,%3}, [%4];"
                 : "=r"(r[0]), "=r"(r[1]), "=r"(r[2]), "=r"(r[3]) : "r"(a));
}
__device__ __forceinline__ void ldsm_x4t(uint32_t* r, uint32_t a) {
    asm volatile("ldmatrix.sync.aligned.m8n8.x4.trans.shared.b16 {%0,%1,%2,%3}, [%4];"
                 : "=r"(r[0]), "=r"(r[1]), "=r"(r[2]), "=r"(r[3]) : "r"(a));
}
__device__ __forceinline__ void mma16816(float* d, const uint32_t* a, const uint32_t* b) {
    asm volatile(
        "mma.sync.aligned.m16n8k16.row.col.f32.bf16.bf16.f32 "
        "{%0,%1,%2,%3}, {%4,%5,%6,%7}, {%8,%9}, {%0,%1,%2,%3};"
        : "+f"(d[0]), "+f"(d[1]), "+f"(d[2]), "+f"(d[3])
        : "r"(a[0]), "r"(a[1]), "r"(a[2]), "r"(a[3]), "r"(b[0]), "r"(b[1]));
}
__device__ __forceinline__ uint32_t packsplit(float x0, float x1, uint32_t& lo) {
    uint32_t h;
    asm("cvt.rn.bf16x2.f32 %0, %1, %2;" : "=r"(h) : "f"(x1), "f"(x0));
    float r0 = x0 - __uint_as_float(h << 16);
    float r1 = x1 - __uint_as_float(h & 0xffff0000u);
    asm("cvt.rn.bf16x2.f32 %0, %1, %2;" : "=r"(lo) : "f"(r1), "f"(r0));
    return h;
}
__device__ __forceinline__ void split4(float4 x, uint2& hi, uint2& lo) {
    uint32_t l0, l1;
    uint32_t h0 = packsplit(x.x, x.y, l0);
    uint32_t h1 = packsplit(x.z, x.w, l1);
    hi = make_uint2(h0, h1);
    lo = make_uint2(l0, l1);
}

// ---------------------------------------------------------------------------
// compute one K=32 chunk: acc[2][2*PC][4] += A(128x32) * B^T, bf16x3 products.
// PC = number of 16-col blocks per warp (4 -> warp tile 32x64, 2 -> 32x32).
// SMEM stage: A hi @0 (pitch 80), A lo @10240, B hi @20480 (pitch BP), B lo @BLO
// ---------------------------------------------------------------------------
template <bool BT, int BLO, int BP, int PC>
__device__ __forceinline__ void compute_chunk(uint32_t sb, int wm, int wn, int lane,
                                              float acc[2][2 * PC][4]) {
    #pragma unroll
    for (int s = 0; s < 2; s++) {
        uint32_t Ah[2][4], Al[2][4];
        uint32_t aaddr = sb + (uint32_t)((wm * 32 + (lane & 15)) * 80
                                         + (s * 16 + (lane >> 4) * 8) * 2);
        ldsm_x4(Ah[0], aaddr);
        ldsm_x4(Ah[1], aaddr + 16 * 80);
        ldsm_x4(Al[0], aaddr + 10240);
        ldsm_x4(Al[1], aaddr + 10240 + 16 * 80);

        #pragma unroll
        for (int p = 0; p < PC; p++) {
            uint32_t rh[4], rl[4], baddr;
            if (!BT) {
                int n  = wn * (16 * PC) + p * 16 + (lane >> 4) * 8 + (lane & 7);
                int kc = s * 16 + ((lane >> 3) & 1) * 8;
                baddr = sb + 20480u + (uint32_t)(n * BP + kc * 2);
                ldsm_x4(rh, baddr);
                ldsm_x4(rl, baddr + (uint32_t)(BLO - 20480));
            } else {
                int k = s * 16 + (lane & 7) + ((lane >> 3) & 1) * 8;
                int n = wn * (16 * PC) + p * 16 + (lane >> 4) * 8;
                baddr = sb + 20480u + (uint32_t)(k * BP + n * 2);
                ldsm_x4t(rh, baddr);
                ldsm_x4t(rl, baddr + (uint32_t)(BLO - 20480));
            }
            mma16816(acc[0][2*p],   Ah[0], &rh[0]);
            mma16816(acc[1][2*p],   Ah[1], &rh[0]);
            mma16816(acc[0][2*p+1], Ah[0], &rh[2]);
            mma16816(acc[1][2*p+1], Ah[1], &rh[2]);
            mma16816(acc[0][2*p],   Ah[0], &rl[0]);
            mma16816(acc[1][2*p],   Ah[1], &rl[0]);
            mma16816(acc[0][2*p+1], Ah[0], &rl[2]);
            mma16816(acc[1][2*p+1], Ah[1], &rl[2]);
            mma16816(acc[0][2*p],   Al[0], &rh[0]);
            mma16816(acc[1][2*p],   Al[1], &rh[0]);
            mma16816(acc[0][2*p+1], Al[0], &rh[2]);
            mma16816(acc[1][2*p+1], Al[1], &rh[2]);
        }
    }
}

#define STRIDE_S 40960   // scores stage: A(2x10240) + B(2x10240)
#define STRIDE_V 30720   // vproj stage:  A(2x10240) + B 64x32 (2x5120)
#define STRIDE_O 29696   // out stage:    S(2x10240) + V 32x64 (2x4608, pitch 144)

// scores stage: A[128x32] hi/lo + B[128x32] hi/lo, both ld=512, pitch 80
__device__ __forceinline__ void stage_s(uint32_t st,
                                        const uint16_t* __restrict__ Ah,
                                        const uint16_t* __restrict__ Al,
                                        const uint16_t* __restrict__ Bh,
                                        const uint16_t* __restrict__ Bl,
                                        int kc, int tid) {
    const uint16_t* srcs[4] = {Ah, Al, Bh, Bl};
    #pragma unroll
    for (int q = 0; q < 8; q++) {
        const int arr = q >> 1;
        const int row = (q & 1) * 64 + (tid >> 2);
        const int seg = tid & 3;
        cp16(st + arr * 10240u + row * 80u + seg * 16u,
             srcs[arr] + (size_t)row * DD + kc + seg * 8);
    }
}

// vproj stage: A[128x32] hi/lo (ld=512) + B[64x32] hi/lo (ld=512), pitch 80
__device__ __forceinline__ void stage_v(uint32_t st,
                                        const uint16_t* __restrict__ Ah,
                                        const uint16_t* __restrict__ Al,
                                        const uint16_t* __restrict__ Bh,
                                        const uint16_t* __restrict__ Bl,
                                        int kc, int tid) {
    #pragma unroll
    for (int q = 0; q < 4; q++) {
        const int arr = q >> 1;
        const int row = (q & 1) * 64 + (tid >> 2);
        const int seg = tid & 3;
        const uint16_t* s = arr ? Al : Ah;
        cp16(st + arr * 10240u + row * 80u + seg * 16u,
             s + (size_t)row * DD + kc + seg * 8);
    }
    {
        const int row = tid >> 2, seg = tid & 3;
        cp16(st + 20480u + row * 80u + seg * 16u, Bh + (size_t)row * DD + kc + seg * 8);
        cp16(st + 25600u + row * 80u + seg * 16u, Bl + (size_t)row * DD + kc + seg * 8);
    }
}

// out stage: S[128x32] hi/lo (ld=2048, pitch 80) + V[32x64] hi/lo (ld=512, pitch 144)
__device__ __forceinline__ void stage_o(uint32_t st,
                                        const uint16_t* __restrict__ Sh,
                                        const uint16_t* __restrict__ Sl,
                                        const uint16_t* __restrict__ Vh,
                                        const uint16_t* __restrict__ Vl,
                                        int kc, int tid) {
    #pragma unroll
    for (int q = 0; q < 4; q++) {
        const int arr = q >> 1;
        const int row = (q & 1) * 64 + (tid >> 2);
        const int seg = tid & 3;
        const uint16_t* s = arr ? Sl : Sh;
        cp16(st + arr * 10240u + row * 80u + seg * 16u,
             s + (size_t)row * NN + kc + seg * 8);
    }
    {
        const int row = tid >> 3, seg = tid & 7;
        cp16(st + 20480u + row * 144u + seg * 16u,
             Vh + (size_t)(kc + row) * DD + seg * 8);
        cp16(st + 25088u + row * 144u + seg * 16u,
             Vl + (size_t)(kc + row) * DD + seg * 8);
    }
}

// ---------------------------------------------------------------------------
// prologue: split X and W to bf16 hi/lo
// ---------------------------------------------------------------------------
__global__ __launch_bounds__(256) void split_kernel(const float* __restrict__ X,
                                                    const float* __restrict__ W) {
    const size_t NX = (size_t)MM * DD / 4;
    const size_t NW = (size_t)DD * DD / 4;
    size_t i = (size_t)blockIdx.x * 256 + threadIdx.x;
    if (i < NX) {
        float4 x = ((const float4*)X)[i];
        uint2 hi, lo; split4(x, hi, lo);
        *(uint2*)(g_Xhi + i * 4) = hi;
        *(uint2*)(g_Xlo + i * 4) = lo;
    } else if (i < NX + NW) {
        size_t j = i - NX;
        float4 x = ((const float4*)W)[j];
        uint2 hi, lo; split4(x, hi, lo);
        *(uint2*)(g_Whi + j * 4) = hi;
        *(uint2*)(g_Wlo + j * 4) = lo;
    }
    if (i < MM) g_rnorm[i] = 0.0f;
}

// ---------------------------------------------------------------------------
// Kernel 1: V = elu(X @ W^T + b) -> g_Vhi/g_Vlo [m][e]
// tile 128x64, 3 CTAs/SM. grid (8, 128)
// ---------------------------------------------------------------------------
__global__ __launch_bounds__(256, 3)
void vproj_kernel(const float* __restrict__ bias) {
    extern __shared__ __align__(16) uint8_t smem[];
    const int tid = threadIdx.x, wid = tid >> 5, lane = tid & 31;
    const int wm = wid & 3, wn = wid >> 2;
    const int eBase = blockIdx.x * 64, mBase = blockIdx.y * 128;
    const uint16_t* Ah = g_Xhi + (size_t)mBase * DD;
    const uint16_t* Al = g_Xlo + (size_t)mBase * DD;
    const uint16_t* Bh = g_Whi + (size_t)eBase * DD;
    const uint16_t* Bl = g_Wlo + (size_t)eBase * DD;
    const uint32_t sb = smem_u32(smem);

    float acc[2][4][4] = {};
    stage_v(sb, Ah, Al, Bh, Bl, 0, tid);  cpcommit();
    for (int c = 0; c < 16; c++) {
        cpwait<0>(); __syncthreads();
        if (c + 1 < 16)
            stage_v(sb + ((c + 1) & 1) * STRIDE_V, Ah, Al, Bh, Bl, (c + 1) * 32, tid);
        cpcommit();
        compute_chunk<false, 25600, 80, 2>(sb + (c & 1) * STRIDE_V, wm, wn, lane, acc);
    }

    // epilogue: bias+elu -> per-warp bounce (32x32, pitch 36) -> coalesced stores
    __syncthreads();
    float* buf = (float*)(smem + wid * 4608);
    const int gr0 = mBase + wm * 32, gc0 = eBase + wn * 32;
    const int r = lane >> 2, cc2 = (lane & 3) * 2;
    #pragma unroll
    for (int mf = 0; mf < 2; mf++)
        #pragma unroll
        for (int nf = 0; nf < 4; nf++) {
            const int col = nf * 8 + cc2;
            float2 bv = *(const float2*)(bias + gc0 + col);
            float v0 = acc[mf][nf][0] + bv.x;
            float v1 = acc[mf][nf][1] + bv.y;
            float v2 = acc[mf][nf][2] + bv.x;
            float v3 = acc[mf][nf][3] + bv.y;
            v0 = v0 > 0.0f ? v0 : expm1f(v0);
            v1 = v1 > 0.0f ? v1 : expm1f(v1);
            v2 = v2 > 0.0f ? v2 : expm1f(v2);
            v3 = v3 > 0.0f ? v3 : expm1f(v3);
            *(float2*)&buf[(mf * 16 + r) * 36 + col]     = make_float2(v0, v1);
            *(float2*)&buf[(mf * 16 + r + 8) * 36 + col] = make_float2(v2, v3);
        }
    __syncwarp();
    #pragma unroll
    for (int it = 0; it < 8; it++) {
        const int row = it * 4 + (lane >> 3);
        const int col = (lane & 7) * 4;
        float4 v = *(float4*)&buf[row * 36 + col];
        uint32_t lo0, lo1;
        uint32_t hi0 = packsplit(v.x, v.y, lo0);
        uint32_t hi1 = packsplit(v.z, v.w, lo1);
        size_t off = (size_t)(gr0 + row) * DD + gc0 + col;
        *(uint2*)(g_Vhi + off) = make_uint2(hi0, hi1);
        *(uint2*)(g_Vlo + off) = make_uint2(lo0, lo1);
    }
}

// ---------------------------------------------------------------------------
// Kernel 2 (symmetric): S = (X X^T / sqrt(D)) * mask, lower-tri tile pairs.
// 128x128 tiles, 2 CTAs/SM. grid (136, 1, 8)
// ---------------------------------------------------------------------------
__global__ __launch_bounds__(256, 2)
void scores_kernel(const float* __restrict__ mask) {
    extern __shared__ __align__(16) uint8_t smem[];
    const int tid = threadIdx.x, wid = tid >> 5, lane = tid & 31;
    const int wm = wid & 3, wn = wid >> 2;
    const int b = blockIdx.z;

    int t = blockIdx.x;
    int tb = (int)((sqrtf(8.0f * t + 1.0f) - 1.0f) * 0.5f);
    while ((tb + 1) * (tb + 2) / 2 <= t) tb++;
    while (tb * (tb + 1) / 2 > t) tb--;
    const int ta = t - tb * (tb + 1) / 2;   // ta <= tb
    const int iBase = ta * 128, jBase = tb * 128;

    const uint16_t* Ah = g_Xhi + (size_t)(b * NN + iBase) * DD;
    const uint16_t* Al = g_Xlo + (size_t)(b * NN + iBase) * DD;
    const uint16_t* Bh = g_Xhi + (size_t)(b * NN + jBase) * DD;
    const uint16_t* Bl = g_Xlo + (size_t)(b * NN + jBase) * DD;
    const float* Mb = mask + (size_t)b * NN * NN;
    uint16_t* Sh = g_Shi + (size_t)b * NN * NN;
    uint16_t* Sl = g_Slo + (size_t)b * NN * NN;
    const uint32_t sb = smem_u32(smem);

    float acc[2][8][4] = {};
    stage_s(sb, Ah, Al, Bh, Bl, 0, tid);  cpcommit();
    for (int c = 0; c < 16; c++) {
        cpwait<0>(); __syncthreads();
        if (c + 1 < 16)
            stage_s(sb + ((c + 1) & 1) * STRIDE_S, Ah, Al, Bh, Bl, (c + 1) * 32, tid);
        cpcommit();
        compute_chunk<false, 30720, 80, 4>(sb + (c & 1) * STRIDE_S, wm, wn, lane, acc);
    }

    // epilogue: raw*invt into per-warp bounce buffer (32 x 64, pitch 68 floats)
    __syncthreads();
    float* buf = (float*)(smem + wid * 8704);
    const int gr0 = iBase + wm * 32, gc0 = jBase + wn * 64;
    const float invt = 0.044194173824159216f;  // 1/sqrt(512)
    {
        const int r = lane >> 2, cc2 = (lane & 3) * 2;
        #pragma unroll
        for (int mf = 0; mf < 2; mf++)
            #pragma unroll
            for (int nf = 0; nf < 8; nf++) {
                const int col = nf * 8 + cc2;
                *(float2*)&buf[(mf * 16 + r) * 68 + col] =
                    make_float2(acc[mf][nf][0] * invt, acc[mf][nf][1] * invt);
                *(float2*)&buf[(mf * 16 + r + 8) * 68 + col] =
                    make_float2(acc[mf][nf][2] * invt, acc[mf][nf][3] * invt);
            }
    }
    __syncwarp();

    // Pass 1: straight orientation (rows i, cols j), mask(i,j), rnorm rows i
    #pragma unroll
    for (int it = 0; it < 16; it++) {
        const int row = it * 2 + (lane >> 4);
        const int col = (lane & 15) * 4;
        const int gi = gr0 + row, gj = gc0 + col;
        float4 m = *(const float4*)(Mb + (size_t)gi * NN + gj);
        float4 v = *(float4*)&buf[row * 68 + col];
        v.x *= m.x; v.y *= m.y; v.z *= m.z; v.w *= m.w;
        float ss = v.x * v.x + v.y * v.y + v.z * v.z + v.w * v.w;
        ss += __shfl_xor_sync(0xffffffffu, ss, 1);
        ss += __shfl_xor_sync(0xffffffffu, ss, 2);
        ss += __shfl_xor_sync(0xffffffffu, ss, 4);
        ss += __shfl_xor_sync(0xffffffffu, ss, 8);
        if ((lane & 15) == 0) atomicAdd(&g_rnorm[b * NN + gi], ss);
        uint32_t lo0, lo1;
        uint32_t hi0 = packsplit(v.x, v.y, lo0);
        uint32_t hi1 = packsplit(v.z, v.w, lo1);
        size_t off = (size_t)gi * NN + gj;
        *(uint2*)(Sh + off) = make_uint2(hi0, hi1);
        *(uint2*)(Sl + off) = make_uint2(lo0, lo1);
    }

    // Pass 2: transposed (rows j, cols i), mask(j,i), rnorm rows j
    if (ta != tb) {
        #pragma unroll
        for (int it = 0; it < 32; it++) {
            const int row2 = it * 2 + (lane >> 4);   // 0..63 (j-local)
            const int col2 = (lane & 15) * 2;        // 0..30 (i-local)
            const int gj2 = gc0 + row2, gi2 = gr0 + col2;
            float2 m = *(const float2*)(Mb + (size_t)gj2 * NN + gi2);
            float s0 = buf[col2 * 68 + row2] * m.x;
            float s1 = buf[(col2 + 1) * 68 + row2] * m.y;
            float ss = s0 * s0 + s1 * s1;
            ss += __shfl_xor_sync(0xffffffffu, ss, 1);
            ss += __shfl_xor_sync(0xffffffffu, ss, 2);
            ss += __shfl_xor_sync(0xffffffffu, ss, 4);
            ss += __shfl_xor_sync(0xffffffffu, ss, 8);
            if ((lane & 15) == 0) atomicAdd(&g_rnorm[b * NN + gj2], ss);
            uint32_t lo0;
            uint32_t hi0 = packsplit(s0, s1, lo0);
            size_t off = (size_t)gj2 * NN + gi2;
            *(uint32_t*)(Sh + off) = hi0;
            *(uint32_t*)(Sl + off) = lo0;
        }
    }
}

// ---------------------------------------------------------------------------
// Kernel 3: out = diag(1/max(||S row||,eps)) * (S @ V)
// tile 128x64, 3 CTAs/SM. grid (8, 16, 8)
// ---------------------------------------------------------------------------
__global__ __launch_bounds__(256, 3)
void out_kernel(float* __restrict__ out) {
    extern __shared__ __align__(16) uint8_t smem[];
    const int tid = threadIdx.x, wid = tid >> 5, lane = tid & 31;
    const int wm = wid & 3, wn = wid >> 2;
    const int b = blockIdx.z;
    const int iBase = blockIdx.y * 128, eBase = blockIdx.x * 64;
    const uint16_t* Sh = g_Shi + (size_t)b * NN * NN + (size_t)iBase * NN;
    const uint16_t* Sl = g_Slo + (size_t)b * NN * NN + (size_t)iBase * NN;
    const uint16_t* Vh = g_Vhi + (size_t)b * NN * DD + eBase;
    const uint16_t* Vl = g_Vlo + (size_t)b * NN * DD + eBase;
    const uint32_t sb = smem_u32(smem);

    float acc[2][4][4] = {};
    stage_o(sb, Sh, Sl, Vh, Vl, 0, tid);  cpcommit();
    for (int c = 0; c < 64; c++) {
        cpwait<0>(); __syncthreads();
        if (c + 1 < 64)
            stage_o(sb + ((c + 1) & 1) * STRIDE_O, Sh, Sl, Vh, Vl, (c + 1) * 32, tid);
        cpcommit();
        compute_chunk<true, 25088, 144, 2>(sb + (c & 1) * STRIDE_O, wm, wn, lane, acc);
    }

    // epilogue: bounce (32x32, pitch 36) + rescale + coalesced f32 stores
    __syncthreads();
    float* buf = (float*)(smem + wid * 4608);
    const int gr0 = iBase + wm * 32, gc0 = eBase + wn * 32;
    const int r = lane >> 2, cc2 = (lane & 3) * 2;
    #pragma unroll
    for (int mf = 0; mf < 2; mf++)
        #pragma unroll
        for (int nf = 0; nf < 4; nf++) {
            const int col = nf * 8 + cc2;
            *(float2*)&buf[(mf * 16 + r) * 36 + col] =
                make_float2(acc[mf][nf][0], acc[mf][nf][1]);
            *(float2*)&buf[(mf * 16 + r + 8) * 36 + col] =
                make_float2(acc[mf][nf][2], acc[mf][nf][3]);
        }
    __syncwarp();
    #pragma unroll
    for (int it = 0; it < 8; it++) {
        const int row = it * 4 + (lane >> 3);
        const int col = (lane & 7) * 4;
        const int gi = gr0 + row;
        float4 v = *(float4*)&buf[row * 36 + col];
        float inv = 1.0f / fmaxf(sqrtf(g_rnorm[b * NN + gi]), NEPS);
        v.x *= inv; v.y *= inv; v.z *= inv; v.w *= inv;
        *(float4*)(out + ((size_t)b * NN + gi) * DD + gc0 + col) = v;
    }
}

// ---------------------------------------------------------------------------
extern "C" void kernel_launch(void* const* d_in, const int* in_sizes, int n_in,
                              void* d_out, int out_size) {
    const float* X    = (const float*)d_in[0];
    const float* mask = (const float*)d_in[1];
    const float* W    = (const float*)d_in[2];
    const float* bias = (const float*)d_in[3];
    float* out = (float*)d_out;

    static int attr_done = 0;
    if (!attr_done) {
        cudaFuncSetAttribute(vproj_kernel,  cudaFuncAttributeMaxDynamicSharedMemorySize, 2 * STRIDE_V);
        cudaFuncSetAttribute(scores_kernel, cudaFuncAttributeMaxDynamicSharedMemorySize, 2 * STRIDE_S);
        cudaFuncSetAttribute(out_kernel,    cudaFuncAttributeMaxDynamicSharedMemorySize, 2 * STRIDE_O);
        attr_done = 1;
    }

    const int NSPLIT = (MM * DD + DD * DD) / 4;
    split_kernel<<<(NSPLIT + 255) / 256, 256>>>(X, W);
    vproj_kernel<<<dim3(8, 128), 256, 2 * STRIDE_V>>>(bias);
    scores_kernel<<<dim3(136, 1, 8), 256, 2 * STRIDE_S>>>(mask);
    out_kernel<<<dim3(8, 16, 8), 256, 2 * STRIDE_O>>>(out);
}

// round 10
// speedup vs baseline: 1.5667x; 1.0336x over previous
#include <cuda_runtime.h>
#include <cuda_bf16.h>
#include <math.h>
#include <stdint.h>

#define BB 8
#define NN 2048
#define DD 512
#define MM (BB * NN)
#define NEPS 1e-5f

// Scratch (__device__ globals — allocation-free per harness rules)
__device__ uint16_t g_Xhi[(size_t)MM * DD];
__device__ uint16_t g_Xlo[(size_t)MM * DD];
__device__ uint16_t g_Whi[(size_t)DD * DD];
__device__ uint16_t g_Wlo[(size_t)DD * DD];
__device__ uint16_t g_Shi[(size_t)BB * NN * NN];
__device__ uint16_t g_Slo[(size_t)BB * NN * NN];
__device__ uint16_t g_Vhi[(size_t)MM * DD];   // V^T: [(b*DD + e)*NN + n]
__device__ uint16_t g_Vlo[(size_t)MM * DD];
__device__ float    g_rnorm[MM];

// ---------------------------------------------------------------------------
// helpers
// ---------------------------------------------------------------------------
__device__ __forceinline__ uint32_t smem_u32(const void* p) {
    uint32_t a;
    asm("{ .reg .u64 t; cvta.to.shared.u64 t, %1; cvt.u32.u64 %0, t; }"
        : "=r"(a) : "l"(p));
    return a;
}
__device__ __forceinline__ void cp16(uint32_t d, const void* g) {
    asm volatile("cp.async.cg.shared.global [%0], [%1], 16;" :: "r"(d), "l"(g));
}
__device__ __forceinline__ void cpcommit() {
    asm volatile("cp.async.commit_group;" ::: "memory");
}
template <int N> __device__ __forceinline__ void cpwait() {
    asm volatile("cp.async.wait_group %0;" :: "n"(N) : "memory");
}
__device__ __forceinline__ void ldsm_x4(uint32_t* r, uint32_t a) {
    asm volatile("ldmatrix.sync.aligned.m8n8.x4.shared.b16 {%0,%1,%2,%3}, [%4];"
                 : "=r"(r[0]), "=r"(r[1]), "=r"(r[2]), "=r"(r[3]) : "r"(a));
}
__device__ __forceinline__ void mma16816(float* d, const uint32_t* a, const uint32_t* b) {
    asm volatile(
        "mma.sync.aligned.m16n8k16.row.col.f32.bf16.bf16.f32 "
        "{%0,%1,%2,%3}, {%4,%5,%6,%7}, {%8,%9}, {%0,%1,%2,%3};"
        : "+f"(d[0]), "+f"(d[1]), "+f"(d[2]), "+f"(d[3])
        : "r"(a[0]), "r"(a[1]), "r"(a[2]), "r"(a[3]), "r"(b[0]), "r"(b[1]));
}
__device__ __forceinline__ uint32_t packsplit(float x0, float x1, uint32_t& lo) {
    uint32_t h;
    asm("cvt.rn.bf16x2.f32 %0, %1, %2;" : "=r"(h) : "f"(x1), "f"(x0));
    float r0 = x0 - __uint_as_float(h << 16);
    float r1 = x1 - __uint_as_float(h & 0xffff0000u);
    asm("cvt.rn.bf16x2.f32 %0, %1, %2;" : "=r"(lo) : "f"(r1), "f"(r0));
    return h;
}
__device__ __forceinline__ void split4(float4 x, uint2& hi, uint2& lo) {
    uint32_t l0, l1;
    uint32_t h0 = packsplit(x.x, x.y, l0);
    uint32_t h1 = packsplit(x.z, x.w, l1);
    hi = make_uint2(h0, h1);
    lo = make_uint2(l0, l1);
}

// ---------------------------------------------------------------------------
// compute one K=32 chunk: acc[2][2*PC][4] += A(128x32) * B^T (B row-major n x k).
// SMEM stage: A hi @0 (pitch 80), A lo @10240, B hi @20480 (pitch 80), B lo @BLO
// ---------------------------------------------------------------------------
template <int BLO, int PC>
__device__ __forceinline__ void compute_chunk(uint32_t sb, int wm, int wn, int lane,
                                              float acc[2][2 * PC][4]) {
    #pragma unroll
    for (int s = 0; s < 2; s++) {
        uint32_t Ah[2][4], Al[2][4];
        uint32_t aaddr = sb + (uint32_t)((wm * 32 + (lane & 15)) * 80
                                         + (s * 16 + (lane >> 4) * 8) * 2);
        ldsm_x4(Ah[0], aaddr);
        ldsm_x4(Ah[1], aaddr + 16 * 80);
        ldsm_x4(Al[0], aaddr + 10240);
        ldsm_x4(Al[1], aaddr + 10240 + 16 * 80);

        #pragma unroll
        for (int p = 0; p < PC; p++) {
            uint32_t rh[4], rl[4];
            int n  = wn * (16 * PC) + p * 16 + (lane >> 4) * 8 + (lane & 7);
            int kc = s * 16 + ((lane >> 3) & 1) * 8;
            uint32_t baddr = sb + 20480u + (uint32_t)(n * 80 + kc * 2);
            ldsm_x4(rh, baddr);
            ldsm_x4(rl, baddr + (uint32_t)(BLO - 20480));
            mma16816(acc[0][2*p],   Ah[0], &rh[0]);
            mma16816(acc[1][2*p],   Ah[1], &rh[0]);
            mma16816(acc[0][2*p+1], Ah[0], &rh[2]);
            mma16816(acc[1][2*p+1], Ah[1], &rh[2]);
            mma16816(acc[0][2*p],   Ah[0], &rl[0]);
            mma16816(acc[1][2*p],   Ah[1], &rl[0]);
            mma16816(acc[0][2*p+1], Ah[0], &rl[2]);
            mma16816(acc[1][2*p+1], Ah[1], &rl[2]);
            mma16816(acc[0][2*p],   Al[0], &rh[0]);
            mma16816(acc[1][2*p],   Al[1], &rh[0]);
            mma16816(acc[0][2*p+1], Al[0], &rh[2]);
            mma16816(acc[1][2*p+1], Al[1], &rh[2]);
        }
    }
}

#define STRIDE_S 40960   // scores stage: A(2x10240) + B(2x10240)
#define STRIDE_V 30720   // vproj/out stage: A(2x10240) + B 64x32 (2x5120)

// scores stage: A[128x32] hi/lo + B[128x32] hi/lo, both ld=512, pitch 80
__device__ __forceinline__ void stage_s(uint32_t st,
                                        const uint16_t* __restrict__ Ah,
                                        const uint16_t* __restrict__ Al,
                                        const uint16_t* __restrict__ Bh,
                                        const uint16_t* __restrict__ Bl,
                                        int kc, int tid) {
    const uint16_t* srcs[4] = {Ah, Al, Bh, Bl};
    #pragma unroll
    for (int q = 0; q < 8; q++) {
        const int arr = q >> 1;
        const int row = (q & 1) * 64 + (tid >> 2);
        const int seg = tid & 3;
        cp16(st + arr * 10240u + row * 80u + seg * 16u,
             srcs[arr] + (size_t)row * DD + kc + seg * 8);
    }
}

// vproj/out stage: A[128x32] hi/lo (ld=LDA) + B[64x32] hi/lo (ld=LDB), pitch 80
__device__ __forceinline__ void stage_v(uint32_t st,
                                        const uint16_t* __restrict__ Ah,
                                        const uint16_t* __restrict__ Al,
                                        const uint16_t* __restrict__ Bh,
                                        const uint16_t* __restrict__ Bl,
                                        int lda, int ldb, int kc, int tid) {
    #pragma unroll
    for (int q = 0; q < 4; q++) {
        const int arr = q >> 1;
        const int row = (q & 1) * 64 + (tid >> 2);
        const int seg = tid & 3;
        const uint16_t* s = arr ? Al : Ah;
        cp16(st + arr * 10240u + row * 80u + seg * 16u,
             s + (size_t)row * lda + kc + seg * 8);
    }
    {
        const int row = tid >> 2, seg = tid & 3;    // row 0..63
        cp16(st + 20480u + row * 80u + seg * 16u, Bh + (size_t)row * ldb + kc + seg * 8);
        cp16(st + 25600u + row * 80u + seg * 16u, Bl + (size_t)row * ldb + kc + seg * 8);
    }
}

// ---------------------------------------------------------------------------
// prologue: split X and W to bf16 hi/lo
// ---------------------------------------------------------------------------
__global__ __launch_bounds__(256) void split_kernel(const float* __restrict__ X,
                                                    const float* __restrict__ W) {
    const size_t NX = (size_t)MM * DD / 4;
    const size_t NW = (size_t)DD * DD / 4;
    size_t i = (size_t)blockIdx.x * 256 + threadIdx.x;
    if (i < NX) {
        float4 x = ((const float4*)X)[i];
        uint2 hi, lo; split4(x, hi, lo);
        *(uint2*)(g_Xhi + i * 4) = hi;
        *(uint2*)(g_Xlo + i * 4) = lo;
    } else if (i < NX + NW) {
        size_t j = i - NX;
        float4 x = ((const float4*)W)[j];
        uint2 hi, lo; split4(x, hi, lo);
        *(uint2*)(g_Whi + j * 4) = hi;
        *(uint2*)(g_Wlo + j * 4) = lo;
    }
    if (i < MM) g_rnorm[i] = 0.0f;
}

// ---------------------------------------------------------------------------
// Kernel 1: V = elu(X @ W^T + b), stored TRANSPOSED: g_Vhi[(b*DD+e)*NN + n]
// tile 128x64, 3 CTAs/SM. grid (8, 128)
// ---------------------------------------------------------------------------
__global__ __launch_bounds__(256, 3)
void vproj_kernel(const float* __restrict__ bias) {
    extern __shared__ __align__(16) uint8_t smem[];
    const int tid = threadIdx.x, wid = tid >> 5, lane = tid & 31;
    const int wm = wid & 3, wn = wid >> 2;
    const int eBase = blockIdx.x * 64, mBase = blockIdx.y * 128;
    const uint16_t* Ah = g_Xhi + (size_t)mBase * DD;
    const uint16_t* Al = g_Xlo + (size_t)mBase * DD;
    const uint16_t* Bh = g_Whi + (size_t)eBase * DD;
    const uint16_t* Bl = g_Wlo + (size_t)eBase * DD;
    const uint32_t sb = smem_u32(smem);

    float acc[2][4][4] = {};
    stage_v(sb, Ah, Al, Bh, Bl, DD, DD, 0, tid);  cpcommit();
    for (int c = 0; c < 16; c++) {
        cpwait<0>(); __syncthreads();
        if (c + 1 < 16)
            stage_v(sb + ((c + 1) & 1) * STRIDE_V, Ah, Al, Bh, Bl, DD, DD, (c + 1) * 32, tid);
        cpcommit();
        compute_chunk<25600, 2>(sb + (c & 1) * STRIDE_V, wm, wn, lane, acc);
    }

    // epilogue: bias+elu -> per-warp bounce (32n x 32e, pitch 34) -> V^T stores
    __syncthreads();
    float* buf = (float*)(smem + wid * 4608);
    const int gr0 = mBase + wm * 32, gc0 = eBase + wn * 32;
    const int bz = mBase >> 11;            // batch
    const int nb0 = (gr0 & (NN - 1));      // n base within batch
    const int r = lane >> 2, cc2 = (lane & 3) * 2;
    #pragma unroll
    for (int mf = 0; mf < 2; mf++)
        #pragma unroll
        for (int nf = 0; nf < 4; nf++) {
            const int col = nf * 8 + cc2;
            float2 bv = *(const float2*)(bias + gc0 + col);
            float v0 = acc[mf][nf][0] + bv.x;
            float v1 = acc[mf][nf][1] + bv.y;
            float v2 = acc[mf][nf][2] + bv.x;
            float v3 = acc[mf][nf][3] + bv.y;
            v0 = v0 > 0.0f ? v0 : expm1f(v0);
            v1 = v1 > 0.0f ? v1 : expm1f(v1);
            v2 = v2 > 0.0f ? v2 : expm1f(v2);
            v3 = v3 > 0.0f ? v3 : expm1f(v3);
            *(float2*)&buf[(mf * 16 + r) * 34 + col]     = make_float2(v0, v1);
            *(float2*)&buf[(mf * 16 + r + 8) * 34 + col] = make_float2(v2, v3);
        }
    __syncwarp();
    // transposed store: rows = e, cols = n (coalesced), scalar column reads
    #pragma unroll
    for (int it = 0; it < 8; it++) {
        const int e  = it * 4 + (lane >> 3);    // 0..31 e-local
        const int n2 = (lane & 7) * 4;          // 0..28 n-local
        float v0 = buf[(n2 + 0) * 34 + e];
        float v1 = buf[(n2 + 1) * 34 + e];
        float v2 = buf[(n2 + 2) * 34 + e];
        float v3 = buf[(n2 + 3) * 34 + e];
        uint32_t lo0, lo1;
        uint32_t hi0 = packsplit(v0, v1, lo0);
        uint32_t hi1 = packsplit(v2, v3, lo1);
        size_t off = ((size_t)bz * DD + gc0 + e) * NN + nb0 + n2;
        *(uint2*)(g_Vhi + off) = make_uint2(hi0, hi1);
        *(uint2*)(g_Vlo + off) = make_uint2(lo0, lo1);
    }
}

// ---------------------------------------------------------------------------
// Kernel 2 (symmetric): S = (X X^T / sqrt(D)) * mask, lower-tri tile pairs.
// 128x128 tiles, 2 CTAs/SM. grid (136, 1, 8)
// ---------------------------------------------------------------------------
__global__ __launch_bounds__(256, 2)
void scores_kernel(const float* __restrict__ mask) {
    extern __shared__ __align__(16) uint8_t smem[];
    const int tid = threadIdx.x, wid = tid >> 5, lane = tid & 31;
    const int wm = wid & 3, wn = wid >> 2;
    const int b = blockIdx.z;

    int t = blockIdx.x;
    int tb = (int)((sqrtf(8.0f * t + 1.0f) - 1.0f) * 0.5f);
    while ((tb + 1) * (tb + 2) / 2 <= t) tb++;
    while (tb * (tb + 1) / 2 > t) tb--;
    const int ta = t - tb * (tb + 1) / 2;   // ta <= tb
    const int iBase = ta * 128, jBase = tb * 128;

    const uint16_t* Ah = g_Xhi + (size_t)(b * NN + iBase) * DD;
    const uint16_t* Al = g_Xlo + (size_t)(b * NN + iBase) * DD;
    const uint16_t* Bh = g_Xhi + (size_t)(b * NN + jBase) * DD;
    const uint16_t* Bl = g_Xlo + (size_t)(b * NN + jBase) * DD;
    const float* Mb = mask + (size_t)b * NN * NN;
    uint16_t* Sh = g_Shi + (size_t)b * NN * NN;
    uint16_t* Sl = g_Slo + (size_t)b * NN * NN;
    const uint32_t sb = smem_u32(smem);

    float acc[2][8][4] = {};
    stage_s(sb, Ah, Al, Bh, Bl, 0, tid);  cpcommit();
    for (int c = 0; c < 16; c++) {
        cpwait<0>(); __syncthreads();
        if (c + 1 < 16)
            stage_s(sb + ((c + 1) & 1) * STRIDE_S, Ah, Al, Bh, Bl, (c + 1) * 32, tid);
        cpcommit();
        compute_chunk<30720, 4>(sb + (c & 1) * STRIDE_S, wm, wn, lane, acc);
    }

    // epilogue: raw*invt into per-warp bounce buffer (32 x 64, pitch 68 floats)
    __syncthreads();
    float* buf = (float*)(smem + wid * 8704);
    const int gr0 = iBase + wm * 32, gc0 = jBase + wn * 64;
    const float invt = 0.044194173824159216f;  // 1/sqrt(512)
    {
        const int r = lane >> 2, cc2 = (lane & 3) * 2;
        #pragma unroll
        for (int mf = 0; mf < 2; mf++)
            #pragma unroll
            for (int nf = 0; nf < 8; nf++) {
                const int col = nf * 8 + cc2;
                *(float2*)&buf[(mf * 16 + r) * 68 + col] =
                    make_float2(acc[mf][nf][0] * invt, acc[mf][nf][1] * invt);
                *(float2*)&buf[(mf * 16 + r + 8) * 68 + col] =
                    make_float2(acc[mf][nf][2] * invt, acc[mf][nf][3] * invt);
            }
    }
    __syncwarp();

    // Pass 1: straight orientation (rows i, cols j), mask(i,j), rnorm rows i
    #pragma unroll
    for (int it = 0; it < 16; it++) {
        const int row = it * 2 + (lane >> 4);
        const int col = (lane & 15) * 4;
        const int gi = gr0 + row, gj = gc0 + col;
        float4 m = *(const float4*)(Mb + (size_t)gi * NN + gj);
        float4 v = *(float4*)&buf[row * 68 + col];
        v.x *= m.x; v.y *= m.y; v.z *= m.z; v.w *= m.w;
        float ss = v.x * v.x + v.y * v.y + v.z * v.z + v.w * v.w;
        ss += __shfl_xor_sync(0xffffffffu, ss, 1);
        ss += __shfl_xor_sync(0xffffffffu, ss, 2);
        ss += __shfl_xor_sync(0xffffffffu, ss, 4);
        ss += __shfl_xor_sync(0xffffffffu, ss, 8);
        if ((lane & 15) == 0) atomicAdd(&g_rnorm[b * NN + gi], ss);
        uint32_t lo0, lo1;
        uint32_t hi0 = packsplit(v.x, v.y, lo0);
        uint32_t hi1 = packsplit(v.z, v.w, lo1);
        size_t off = (size_t)gi * NN + gj;
        *(uint2*)(Sh + off) = make_uint2(hi0, hi1);
        *(uint2*)(Sl + off) = make_uint2(lo0, lo1);
    }

    // Pass 2: transposed (rows j, cols i), mask(j,i), rnorm rows j
    if (ta != tb) {
        #pragma unroll
        for (int it = 0; it < 32; it++) {
            const int row2 = it * 2 + (lane >> 4);   // 0..63 (j-local)
            const int col2 = (lane & 15) * 2;        // 0..30 (i-local)
            const int gj2 = gc0 + row2, gi2 = gr0 + col2;
            float2 m = *(const float2*)(Mb + (size_t)gj2 * NN + gi2);
            float s0 = buf[col2 * 68 + row2] * m.x;
            float s1 = buf[(col2 + 1) * 68 + row2] * m.y;
            float ss = s0 * s0 + s1 * s1;
            ss += __shfl_xor_sync(0xffffffffu, ss, 1);
            ss += __shfl_xor_sync(0xffffffffu, ss, 2);
            ss += __shfl_xor_sync(0xffffffffu, ss, 4);
            ss += __shfl_xor_sync(0xffffffffu, ss, 8);
            if ((lane & 15) == 0) atomicAdd(&g_rnorm[b * NN + gj2], ss);
            uint32_t lo0;
            uint32_t hi0 = packsplit(s0, s1, lo0);
            size_t off = (size_t)gj2 * NN + gi2;
            *(uint32_t*)(Sh + off) = hi0;
            *(uint32_t*)(Sl + off) = lo0;
        }
    }
}

// ---------------------------------------------------------------------------
// Kernel 3: out = diag(1/max(||S row||,eps)) * (S @ V), V^T layout (non-trans B)
// tile 128x64, 3 CTAs/SM. grid (8, 16, 8)
// ---------------------------------------------------------------------------
__global__ __launch_bounds__(256, 3)
void out_kernel(float* __restrict__ out) {
    extern __shared__ __align__(16) uint8_t smem[];
    const int tid = threadIdx.x, wid = tid >> 5, lane = tid & 31;
    const int wm = wid & 3, wn = wid >> 2;
    const int b = blockIdx.z;
    const int iBase = blockIdx.y * 128, eBase = blockIdx.x * 64;
    const uint16_t* Sh = g_Shi + (size_t)b * NN * NN + (size_t)iBase * NN;
    const uint16_t* Sl = g_Slo + (size_t)b * NN * NN + (size_t)iBase * NN;
    const uint16_t* Vh = g_Vhi + ((size_t)b * DD + eBase) * NN;   // V^T rows = e
    const uint16_t* Vl = g_Vlo + ((size_t)b * DD + eBase) * NN;
    const uint32_t sb = smem_u32(smem);

    float acc[2][4][4] = {};
    stage_v(sb, Sh, Sl, Vh, Vl, NN, NN, 0, tid);  cpcommit();
    for (int c = 0; c < 64; c++) {
        cpwait<0>(); __syncthreads();
        if (c + 1 < 64)
            stage_v(sb + ((c + 1) & 1) * STRIDE_V, Sh, Sl, Vh, Vl, NN, NN, (c + 1) * 32, tid);
        cpcommit();
        compute_chunk<25600, 2>(sb + (c & 1) * STRIDE_V, wm, wn, lane, acc);
    }

    // epilogue: bounce (32x32, pitch 36) + rescale + coalesced f32 stores
    __syncthreads();
    float* buf = (float*)(smem + wid * 4608);
    const int gr0 = iBase + wm * 32, gc0 = eBase + wn * 32;
    const int r = lane >> 2, cc2 = (lane & 3) * 2;
    #pragma unroll
    for (int mf = 0; mf < 2; mf++)
        #pragma unroll
        for (int nf = 0; nf < 4; nf++) {
            const int col = nf * 8 + cc2;
            *(float2*)&buf[(mf * 16 + r) * 36 + col] =
                make_float2(acc[mf][nf][0], acc[mf][nf][1]);
            *(float2*)&buf[(mf * 16 + r + 8) * 36 + col] =
                make_float2(acc[mf][nf][2], acc[mf][nf][3]);
        }
    __syncwarp();
    #pragma unroll
    for (int it = 0; it < 8; it++) {
        const int row = it * 4 + (lane >> 3);
        const int col = (lane & 7) * 4;
        const int gi = gr0 + row;
        float4 v = *(float4*)&buf[row * 36 + col];
        float inv = 1.0f / fmaxf(sqrtf(g_rnorm[b * NN + gi]), NEPS);
        v.x *= inv; v.y *= inv; v.z *= inv; v.w *= inv;
        *(float4*)(out + ((size_t)b * NN + gi) * DD + gc0 + col) = v;
    }
}

// ---------------------------------------------------------------------------
extern "C" void kernel_launch(void* const* d_in, const int* in_sizes, int n_in,
                              void* d_out, int out_size) {
    const float* X    = (const float*)d_in[0];
    const float* mask = (const float*)d_in[1];
    const float* W    = (const float*)d_in[2];
    const float* bias = (const float*)d_in[3];
    float* out = (float*)d_out;

    static cudaStream_t s2 = nullptr;
    static cudaEvent_t evA = nullptr, evB = nullptr;
    static int attr_done = 0;
    if (!attr_done) {
        cudaFuncSetAttribute(vproj_kernel,  cudaFuncAttributeMaxDynamicSharedMemorySize, 2 * STRIDE_V);
        cudaFuncSetAttribute(scores_kernel, cudaFuncAttributeMaxDynamicSharedMemorySize, 2 * STRIDE_S);
        cudaFuncSetAttribute(out_kernel,    cudaFuncAttributeMaxDynamicSharedMemorySize, 2 * STRIDE_V);
        cudaStreamCreateWithFlags(&s2, cudaStreamNonBlocking);
        cudaEventCreateWithFlags(&evA, cudaEventDisableTiming);
        cudaEventCreateWithFlags(&evB, cudaEventDisableTiming);
        attr_done = 1;
    }

    const int NSPLIT = (MM * DD + DD * DD) / 4;
    split_kernel<<<(NSPLIT + 255) / 256, 256>>>(X, W);

    // fork: vproj on s2, scores on default stream
    cudaEventRecord(evA, 0);
    cudaStreamWaitEvent(s2, evA, 0);
    vproj_kernel<<<dim3(8, 128), 256, 2 * STRIDE_V, s2>>>(bias);
    cudaEventRecord(evB, s2);

    scores_kernel<<<dim3(136, 1, 8), 256, 2 * STRIDE_S>>>(mask);

    // join: out depends on both
    cudaStreamWaitEvent(0, evB, 0);
    out_kernel<<<dim3(8, 16, 8), 256, 2 * STRIDE_V>>>(out);
}